// round 3
// baseline (speedup 1.0000x reference)
#include <cuda_runtime.h>
#include <math.h>

#define BB 4
#define SS 2048
#define DD 768
#define HH 12
#define HD 64

// Scratch (B*H*S*HD = 6,291,456 floats each = 24 MB)
__device__ float g_q[BB * HH * SS * HD];
__device__ float g_k[BB * HH * SS * HD];
__device__ float g_v[BB * HH * SS * HD];
__device__ float g_ctx[BB * SS * DD];

// ---------------------------------------------------------------------------
// GEMM: C[M,N] = A[M,K] * W[N,K]^T (+bias), M=8192, N=768, K=768
// 64x64 tile, BK=16, 256 threads, 4x4 micro-tile per thread.
// mode: 0 = out-proj (reads g_ctx, bias, writes `out`)
//       1/2/3 = Q/K/V projection (reads `A`, scatters into g_q/g_k/g_v)
// ---------------------------------------------------------------------------
__global__ __launch_bounds__(256) void gemm64(
    const float* __restrict__ A, const float* __restrict__ W,
    const float* __restrict__ bias, float* __restrict__ out, int mode)
{
    __shared__ float As[16][64];   // [k][m], conflict-free stores/loads
    __shared__ float Bs[16][64];   // [k][n]

    const int t  = threadIdx.x;
    const int tx = t & 15, ty = t >> 4;
    const int r  = t & 63, c4 = (t >> 6) * 4;     // loader mapping
    const int m0 = blockIdx.y * 64, n0 = blockIdx.x * 64;

    const float* Asrc = (mode == 0) ? g_ctx : A;
    const float* Ag = Asrc + (size_t)(m0 + r) * DD;
    const float* Wg = W + (size_t)(n0 + r) * DD;

    float acc[4][4] = {};

    // prefetch first K-slab
    float4 av = *(const float4*)(Ag + c4);
    float4 wv = *(const float4*)(Wg + c4);

    for (int k0 = 0; k0 < DD; k0 += 16) {
        __syncthreads();
        As[c4 + 0][r] = av.x; As[c4 + 1][r] = av.y;
        As[c4 + 2][r] = av.z; As[c4 + 3][r] = av.w;
        Bs[c4 + 0][r] = wv.x; Bs[c4 + 1][r] = wv.y;
        Bs[c4 + 2][r] = wv.z; Bs[c4 + 3][r] = wv.w;
        __syncthreads();

        if (k0 + 16 < DD) {  // prefetch next slab, overlap with compute
            av = *(const float4*)(Ag + k0 + 16 + c4);
            wv = *(const float4*)(Wg + k0 + 16 + c4);
        }

        #pragma unroll
        for (int kk = 0; kk < 16; kk++) {
            float4 a = *(const float4*)&As[kk][4 * ty];
            float4 b = *(const float4*)&Bs[kk][4 * tx];
            acc[0][0] += a.x * b.x; acc[0][1] += a.x * b.y;
            acc[0][2] += a.x * b.z; acc[0][3] += a.x * b.w;
            acc[1][0] += a.y * b.x; acc[1][1] += a.y * b.y;
            acc[1][2] += a.y * b.z; acc[1][3] += a.y * b.w;
            acc[2][0] += a.z * b.x; acc[2][1] += a.z * b.y;
            acc[2][2] += a.z * b.z; acc[2][3] += a.z * b.w;
            acc[3][0] += a.w * b.x; acc[3][1] += a.w * b.y;
            acc[3][2] += a.w * b.z; acc[3][3] += a.w * b.w;
        }
    }

    if (mode != 0) {
        // head-scatter into [B,H,S,HD]: n tile = exactly one head (64 wide)
        float* dst = (mode == 1) ? g_q : (mode == 2) ? g_k : g_v;
        const int h = n0 >> 6;
        const int d = 4 * tx;
        #pragma unroll
        for (int i = 0; i < 4; i++) {
            int m = m0 + 4 * ty + i;
            int b = m >> 11, s = m & (SS - 1);
            float4 v = make_float4(acc[i][0], acc[i][1], acc[i][2], acc[i][3]);
            *(float4*)(dst + (size_t)(((b * HH + h) * SS) + s) * HD + d) = v;
        }
    } else {
        float4 bv = *(const float4*)(bias + n0 + 4 * tx);
        #pragma unroll
        for (int i = 0; i < 4; i++) {
            int m = m0 + 4 * ty + i;
            float4 v = make_float4(acc[i][0] + bv.x, acc[i][1] + bv.y,
                                   acc[i][2] + bv.z, acc[i][3] + bv.w);
            *(float4*)(out + (size_t)m * DD + n0 + 4 * tx) = v;
        }
    }
}

// ---------------------------------------------------------------------------
// Flash attention, causal. One block per (q-tile of 64 rows, b*h).
// 256 threads; O accumulator 4x4 per thread; fp32 online softmax.
// Reads g_q/g_k/g_v, writes g_ctx.
// ---------------------------------------------------------------------------
#define ATTN_SMEM ((4 * 4096 + 3 * 64) * 4)

__global__ __launch_bounds__(256) void attn_kernel()
{
    extern __shared__ float sm[];
    float* Qt  = sm;              // [64 d][64 r]  (d-major)
    float* Kt  = Qt + 4096;       // [64 d][64 c]
    float* Vs  = Kt + 4096;       // [64 j][64 c]  (natural)
    float* Ps  = Vs + 4096;       // [64 r][64 c]
    float* mrow = Ps + 4096;      // [64]
    float* lrow = mrow + 64;      // [64]
    float* arow = lrow + 64;      // [64]

    const int t  = threadIdx.x;
    const int tx = t & 15, ty = t >> 4;
    const int r  = t & 63, c4 = (t >> 6) * 4;
    const int qt = blockIdx.x;
    const int bh = blockIdx.y;

    const float* Qg  = g_q + ((size_t)bh * SS + qt * 64) * HD;
    const float* Kg0 = g_k + (size_t)bh * SS * HD;
    const float* Vg0 = g_v + (size_t)bh * SS * HD;

    // Load Q transposed (d-major): conflict-free smem stores
    #pragma unroll
    for (int j = 0; j < 4; j++) {
        int d0 = j * 16 + c4;
        float4 v = *(const float4*)(Qg + r * HD + d0);
        Qt[(d0 + 0) * 64 + r] = v.x; Qt[(d0 + 1) * 64 + r] = v.y;
        Qt[(d0 + 2) * 64 + r] = v.z; Qt[(d0 + 3) * 64 + r] = v.w;
    }
    if (t < 64) { mrow[t] = -INFINITY; lrow[t] = 0.0f; }

    float o[4][4] = {};
    const int ntiles = qt + 1;
    const float scale = 0.125f;   // 1/sqrt(64)

    for (int kt = 0; kt < ntiles; kt++) {
        const float* Kg = Kg0 + (size_t)kt * 64 * HD;
        const float* Vg = Vg0 + (size_t)kt * 64 * HD;

        __syncthreads();  // previous iter done with Kt/Vs/Ps
        #pragma unroll
        for (int j = 0; j < 4; j++) {
            int d0 = j * 16 + c4;
            float4 v = *(const float4*)(Kg + r * HD + d0);
            Kt[(d0 + 0) * 64 + r] = v.x; Kt[(d0 + 1) * 64 + r] = v.y;
            Kt[(d0 + 2) * 64 + r] = v.z; Kt[(d0 + 3) * 64 + r] = v.w;
        }
        #pragma unroll
        for (int j = 0; j < 16; j++) {  // natural copy, fully coalesced
            int idx = j * 256 + t;
            Vs[idx] = Vg[idx];
        }
        __syncthreads();

        // S = Q * K^T  (4x4 micro-tile)
        float s[4][4] = {};
        #pragma unroll
        for (int d = 0; d < 64; d++) {
            float4 a = *(const float4*)&Qt[d * 64 + 4 * ty];
            float4 b = *(const float4*)&Kt[d * 64 + 4 * tx];
            s[0][0] += a.x * b.x; s[0][1] += a.x * b.y; s[0][2] += a.x * b.z; s[0][3] += a.x * b.w;
            s[1][0] += a.y * b.x; s[1][1] += a.y * b.y; s[1][2] += a.y * b.z; s[1][3] += a.y * b.w;
            s[2][0] += a.z * b.x; s[2][1] += a.z * b.y; s[2][2] += a.z * b.z; s[2][3] += a.z * b.w;
            s[3][0] += a.w * b.x; s[3][1] += a.w * b.y; s[3][2] += a.w * b.z; s[3][3] += a.w * b.w;
        }

        const bool diag = (kt == qt);
        #pragma unroll
        for (int i = 0; i < 4; i++) {
            int row = 4 * ty + i;
            float4 v;
            v.x = s[i][0] * scale; v.y = s[i][1] * scale;
            v.z = s[i][2] * scale; v.w = s[i][3] * scale;
            if (diag) {
                int c = 4 * tx;
                if (c + 0 > row) v.x = -INFINITY;
                if (c + 1 > row) v.y = -INFINITY;
                if (c + 2 > row) v.z = -INFINITY;
                if (c + 3 > row) v.w = -INFINITY;
            }
            *(float4*)&Ps[row * 64 + 4 * tx] = v;
        }
        __syncthreads();

        // Row stats: 4 lanes per row, 16 cols each
        {
            const int row = t >> 2, q = t & 3;
            float* p = &Ps[row * 64 + q * 16];
            float mx = -INFINITY;
            #pragma unroll
            for (int j = 0; j < 16; j++) mx = fmaxf(mx, p[j]);
            mx = fmaxf(mx, __shfl_xor_sync(0xffffffffu, mx, 1));
            mx = fmaxf(mx, __shfl_xor_sync(0xffffffffu, mx, 2));
            const float mo = mrow[row];
            const float mn = fmaxf(mo, mx);
            float sum = 0.0f;
            #pragma unroll
            for (int j = 0; j < 16; j++) {
                float e = __expf(p[j] - mn);
                p[j] = e;
                sum += e;
            }
            sum += __shfl_xor_sync(0xffffffffu, sum, 1);
            sum += __shfl_xor_sync(0xffffffffu, sum, 2);
            if (q == 0) {
                float al = __expf(mo - mn);
                arow[row] = al;
                lrow[row] = lrow[row] * al + sum;
                mrow[row] = mn;
            }
        }
        __syncthreads();

        // Rescale O, then O += P * V (P rows read as float4 to cut LDS count)
        float al[4];
        #pragma unroll
        for (int i = 0; i < 4; i++) al[i] = arow[4 * ty + i];
        #pragma unroll
        for (int i = 0; i < 4; i++) {
            o[i][0] *= al[i]; o[i][1] *= al[i]; o[i][2] *= al[i]; o[i][3] *= al[i];
        }
        #pragma unroll
        for (int k4 = 0; k4 < 64; k4 += 4) {
            float4 p0 = *(const float4*)&Ps[(4 * ty + 0) * 64 + k4];
            float4 p1 = *(const float4*)&Ps[(4 * ty + 1) * 64 + k4];
            float4 p2 = *(const float4*)&Ps[(4 * ty + 2) * 64 + k4];
            float4 p3 = *(const float4*)&Ps[(4 * ty + 3) * 64 + k4];
            #pragma unroll
            for (int u = 0; u < 4; u++) {
                float4 b = *(const float4*)&Vs[(k4 + u) * 64 + 4 * tx];
                float a0 = (&p0.x)[u], a1 = (&p1.x)[u], a2 = (&p2.x)[u], a3 = (&p3.x)[u];
                o[0][0] += a0 * b.x; o[0][1] += a0 * b.y; o[0][2] += a0 * b.z; o[0][3] += a0 * b.w;
                o[1][0] += a1 * b.x; o[1][1] += a1 * b.y; o[1][2] += a1 * b.z; o[1][3] += a1 * b.w;
                o[2][0] += a2 * b.x; o[2][1] += a2 * b.y; o[2][2] += a2 * b.z; o[2][3] += a2 * b.w;
                o[3][0] += a3 * b.x; o[3][1] += a3 * b.y; o[3][2] += a3 * b.z; o[3][3] += a3 * b.w;
            }
        }
    }

    // Epilogue: normalize, write ctx in [B,S,D] layout
    const int h = bh % HH, b = bh / HH;
    #pragma unroll
    for (int i = 0; i < 4; i++) {
        int row = 4 * ty + i;
        int sidx = qt * 64 + row;
        float inv = 1.0f / lrow[row];
        float4 v = make_float4(o[i][0] * inv, o[i][1] * inv,
                               o[i][2] * inv, o[i][3] * inv);
        *(float4*)(g_ctx + ((size_t)b * SS + sidx) * DD + h * HD + 4 * tx) = v;
    }
}

// ---------------------------------------------------------------------------
extern "C" void kernel_launch(void* const* d_in, const int* in_sizes, int n_in,
                              void* d_out, int out_size)
{
    const float* x  = (const float*)d_in[0];
    const float* wq = (const float*)d_in[1];
    const float* wk = (const float*)d_in[2];
    const float* wv = (const float*)d_in[3];
    const float* wo = (const float*)d_in[4];
    const float* bo = (const float*)d_in[5];
    float* out = (float*)d_out;

    static int smem_set = 0;
    if (!smem_set) {
        cudaFuncSetAttribute(attn_kernel,
                             cudaFuncAttributeMaxDynamicSharedMemorySize, ATTN_SMEM);
        smem_set = 1;
    }

    dim3 blk(256);
    dim3 gproj(DD / 64, (BB * SS) / 64);   // (12, 128)

    gemm64<<<gproj, blk>>>(x, wq, nullptr, nullptr, 1);
    gemm64<<<gproj, blk>>>(x, wk, nullptr, nullptr, 2);
    gemm64<<<gproj, blk>>>(x, wv, nullptr, nullptr, 3);

    attn_kernel<<<dim3(SS / 64, BB * HH), blk, ATTN_SMEM>>>();

    gemm64<<<gproj, blk>>>(nullptr, wo, bo, out, 0);
}

// round 4
// speedup vs baseline: 2.9165x; 2.9165x over previous
#include <cuda_runtime.h>
#include <math.h>
#include <stdint.h>

#define BB 4
#define SS 2048
#define DD 768
#define HH 12
#define HD 64

// Scratch
__device__ float g_q  [BB*HH*SS*HD];   // [bh][s][d]
__device__ float g_k  [BB*HH*SS*HD];   // [bh][s][d]
__device__ float g_vt [BB*HH*HD*SS];   // [bh][d][s]  (transposed V!)
__device__ float g_ctx[BB*SS*DD];      // [b][s][D]

__device__ __forceinline__ uint32_t f2tf(float x) {
    uint32_t u; asm("cvt.rna.tf32.f32 %0, %1;" : "=r"(u) : "f"(x)); return u;
}

// D += A(16x8,row) * B(8x8,col), tf32 in, f32 accum
__device__ __forceinline__ void mma8(float* c, uint32_t a0, uint32_t a1,
                                     uint32_t a2, uint32_t a3,
                                     uint32_t b0, uint32_t b1) {
    asm volatile(
        "mma.sync.aligned.m16n8k8.row.col.f32.tf32.tf32.f32 "
        "{%0,%1,%2,%3}, {%4,%5,%6,%7}, {%8,%9}, {%0,%1,%2,%3};"
        : "+f"(c[0]), "+f"(c[1]), "+f"(c[2]), "+f"(c[3])
        : "r"(a0), "r"(a1), "r"(a2), "r"(a3), "r"(b0), "r"(b1));
}

// ---------------------------------------------------------------------------
// TF32 GEMM: C[M,N] = A[M,K] @ W[N,K]^T.  M=8192, N=768, K=768.
// Block 128x128, BK=16, 256 threads = 8 warps (2m x 4n), warp tile 64x32.
// Smem: interleaved tf32, row stride 24 floats -> conflict-free LDS.64 frags.
// mode: 0 = out-proj (A=g_ctx, +bias -> out)
//       1/2 = Q/K proj -> g_q/g_k [bh][s][d]
//       3 = V proj -> g_vt [bh][d][s]   (transposed epilogue)
// ---------------------------------------------------------------------------
__global__ __launch_bounds__(256) void gemm_tc(
    const float* __restrict__ A, const float* __restrict__ W,
    const float* __restrict__ bias, float* __restrict__ out, int mode)
{
    __shared__ uint32_t As[128*24];
    __shared__ uint32_t Bs[128*24];

    const int t = threadIdx.x;
    const int lane = t & 31;
    const int q = lane & 3, g = lane >> 2;
    const int warp = t >> 5;
    const int wm = warp & 1, wn = warp >> 1;
    const int m0 = blockIdx.y * 128, n0 = blockIdx.x * 128;

    const int lrow = t >> 2;            // 0..63
    const int lc4  = (t & 3) * 4;       // 0,4,8,12
    const int sb   = (lc4 & 8) + ((lc4 >> 2) & 1);  // interleaved col base

    const float* Ap = (mode == 0) ? (const float*)g_ctx : A;
    const float* Ag0 = Ap + (size_t)(m0 + lrow) * DD + lc4;
    const float* Ag1 = Ag0 + (size_t)64 * DD;
    const float* Wg0 = W + (size_t)(n0 + lrow) * DD + lc4;
    const float* Wg1 = Wg0 + (size_t)64 * DD;

    float c[4][4][4] = {};

    float4 pa0 = *(const float4*)Ag0;
    float4 pa1 = *(const float4*)Ag1;
    float4 pb0 = *(const float4*)Wg0;
    float4 pb1 = *(const float4*)Wg1;

    for (int k0 = 0; k0 < DD; k0 += 16) {
        __syncthreads();
        {
            uint32_t* d0 = &As[lrow * 24 + sb];
            d0[0] = f2tf(pa0.x); d0[2] = f2tf(pa0.y);
            d0[4] = f2tf(pa0.z); d0[6] = f2tf(pa0.w);
            uint32_t* d1 = &As[(lrow + 64) * 24 + sb];
            d1[0] = f2tf(pa1.x); d1[2] = f2tf(pa1.y);
            d1[4] = f2tf(pa1.z); d1[6] = f2tf(pa1.w);
            uint32_t* d2 = &Bs[lrow * 24 + sb];
            d2[0] = f2tf(pb0.x); d2[2] = f2tf(pb0.y);
            d2[4] = f2tf(pb0.z); d2[6] = f2tf(pb0.w);
            uint32_t* d3 = &Bs[(lrow + 64) * 24 + sb];
            d3[0] = f2tf(pb1.x); d3[2] = f2tf(pb1.y);
            d3[4] = f2tf(pb1.z); d3[6] = f2tf(pb1.w);
        }
        __syncthreads();
        if (k0 + 16 < DD) {
            pa0 = *(const float4*)(Ag0 + k0 + 16);
            pa1 = *(const float4*)(Ag1 + k0 + 16);
            pb0 = *(const float4*)(Wg0 + k0 + 16);
            pb1 = *(const float4*)(Wg1 + k0 + 16);
        }
        #pragma unroll
        for (int ks = 0; ks < 2; ks++) {
            uint2 a[4][2]; uint2 b[4];
            #pragma unroll
            for (int mt = 0; mt < 4; mt++) {
                int r = wm * 64 + mt * 16 + g;
                a[mt][0] = *(const uint2*)&As[r * 24 + ks * 8 + 2 * q];
                a[mt][1] = *(const uint2*)&As[(r + 8) * 24 + ks * 8 + 2 * q];
            }
            #pragma unroll
            for (int nt = 0; nt < 4; nt++) {
                int r = wn * 32 + nt * 8 + g;
                b[nt] = *(const uint2*)&Bs[r * 24 + ks * 8 + 2 * q];
            }
            #pragma unroll
            for (int mt = 0; mt < 4; mt++)
                #pragma unroll
                for (int nt = 0; nt < 4; nt++)
                    mma8(c[mt][nt], a[mt][0].x, a[mt][1].x, a[mt][0].y, a[mt][1].y,
                         b[nt].x, b[nt].y);
        }
    }

    // Epilogue
    #pragma unroll
    for (int mt = 0; mt < 4; mt++) {
        const int r0 = m0 + wm * 64 + mt * 16 + g;   // r1 = r0+8, same batch
        #pragma unroll
        for (int nt = 0; nt < 4; nt++) {
            const int cc = n0 + wn * 32 + nt * 8 + 2 * q;
            if (mode == 0) {
                float2 bv = *(const float2*)(bias + cc);
                *(float2*)(out + (size_t)r0 * DD + cc) =
                    make_float2(c[mt][nt][0] + bv.x, c[mt][nt][1] + bv.y);
                *(float2*)(out + (size_t)(r0 + 8) * DD + cc) =
                    make_float2(c[mt][nt][2] + bv.x, c[mt][nt][3] + bv.y);
            } else {
                const int h = cc >> 6, d = cc & 63;
                const int bi = r0 >> 11, s0 = r0 & (SS - 1), s1 = s0 + 8;
                if (mode == 3) {
                    float* dst = g_vt + ((size_t)((bi * HH + h) * HD + d)) * SS;
                    dst[s0]      = c[mt][nt][0];
                    dst[SS + s0] = c[mt][nt][1];
                    dst[s1]      = c[mt][nt][2];
                    dst[SS + s1] = c[mt][nt][3];
                } else {
                    float* dst = (mode == 1) ? g_q : g_k;
                    *(float2*)(dst + ((size_t)(bi * HH + h) * SS + s0) * HD + d) =
                        make_float2(c[mt][nt][0], c[mt][nt][1]);
                    *(float2*)(dst + ((size_t)(bi * HH + h) * SS + s1) * HD + d) =
                        make_float2(c[mt][nt][2], c[mt][nt][3]);
                }
            }
        }
    }
}

// ---------------------------------------------------------------------------
// TF32 flash attention, causal. Block = 64 q-rows x 64 kv, 256 thr = 8 warps
// (4m x 2n); warp tile 16x32. Fragment softmax + smem row stats.
// ---------------------------------------------------------------------------
#define ATTN_SMEM_BYTES (18880 * 4)

__global__ __launch_bounds__(256) void attn_tc()
{
    extern __shared__ float sm[];
    float* Qs   = sm;            // [64][72] tf32, interleaved
    float* Ks   = sm + 4608;     // [64][72]
    float* Vt   = sm + 9216;     // [64 d][72 j]  (B for PV)
    float* Ps   = sm + 13824;    // [64][72]
    float* mrow = sm + 18432;    // [64]
    float* lrw  = sm + 18496;    // [64]
    float* arow = sm + 18560;    // [64]
    float* pmax = sm + 18624;    // [2][64]
    float* psum = sm + 18752;    // [2][64]

    const int t = threadIdx.x;
    const int lane = t & 31;
    const int q = lane & 3, g = lane >> 2;
    const int warp = t >> 5;
    const int wm = warp & 3, wn = warp >> 2;
    const int qt = blockIdx.x, bh = blockIdx.y;

    const int d4  = (t & 15) * 4;
    const int r0l = t >> 4;                       // 0..15
    const int sb  = (d4 >> 3) * 8 + ((d4 >> 2) & 1);

    // Q load (pre-scaled by 1/sqrt(64)=0.125, exact in tf32)
    {
        const float* Qg = g_q + ((size_t)bh * SS + qt * 64) * HD;
        #pragma unroll
        for (int i = 0; i < 4; i++) {
            int r = r0l + 16 * i;
            float4 v = *(const float4*)(Qg + r * HD + d4);
            uint32_t* dst = (uint32_t*)&Qs[r * 72 + sb];
            dst[0] = f2tf(v.x * 0.125f); dst[2] = f2tf(v.y * 0.125f);
            dst[4] = f2tf(v.z * 0.125f); dst[6] = f2tf(v.w * 0.125f);
        }
    }
    if (t < 64) { mrow[t] = -INFINITY; lrw[t] = 0.0f; }

    float o[4][4] = {};

    const float* Kg0 = g_k  + (size_t)bh * SS * HD;
    const float* Vg0 = g_vt + (size_t)bh * HD * SS;

    const int rbase = wm * 16 + g;
    const int aoff  = rbase * 72 + 2 * q;

    for (int kt = 0; kt <= qt; kt++) {
        __syncthreads();
        {
            const float* Kg = Kg0 + (size_t)kt * 64 * HD;
            #pragma unroll
            for (int i = 0; i < 4; i++) {
                int r = r0l + 16 * i;
                float4 v = *(const float4*)(Kg + r * HD + d4);
                uint32_t* dst = (uint32_t*)&Ks[r * 72 + sb];
                dst[0] = f2tf(v.x); dst[2] = f2tf(v.y);
                dst[4] = f2tf(v.z); dst[6] = f2tf(v.w);
            }
            #pragma unroll
            for (int i = 0; i < 4; i++) {
                int d = r0l + 16 * i;
                float4 v = *(const float4*)(Vg0 + (size_t)d * SS + kt * 64 + d4);
                uint32_t* dst = (uint32_t*)&Vt[d * 72 + sb];
                dst[0] = f2tf(v.x); dst[2] = f2tf(v.y);
                dst[4] = f2tf(v.z); dst[6] = f2tf(v.w);
            }
        }
        __syncthreads();

        // S = Q K^T (per-warp 16x32)
        float s4[4][4];
        #pragma unroll
        for (int nt = 0; nt < 4; nt++) {
            s4[nt][0] = 0.f; s4[nt][1] = 0.f; s4[nt][2] = 0.f; s4[nt][3] = 0.f;
        }
        #pragma unroll
        for (int ks = 0; ks < 8; ks++) {
            uint2 alo = *(const uint2*)&Qs[aoff + ks * 8];
            uint2 ahi = *(const uint2*)&Qs[aoff + 8 * 72 + ks * 8];
            #pragma unroll
            for (int nt = 0; nt < 4; nt++) {
                uint2 b = *(const uint2*)&Ks[(wn * 32 + nt * 8 + g) * 72 + ks * 8 + 2 * q];
                mma8(s4[nt], alo.x, ahi.x, alo.y, ahi.y, b.x, b.y);
            }
        }

        if (kt == qt) {  // causal mask on the diagonal tile (local row/col compare)
            const int row0 = rbase, row1 = rbase + 8;
            #pragma unroll
            for (int nt = 0; nt < 4; nt++) {
                int col = wn * 32 + nt * 8 + 2 * q;
                if (col     > row0) s4[nt][0] = -INFINITY;
                if (col + 1 > row0) s4[nt][1] = -INFINITY;
                if (col     > row1) s4[nt][2] = -INFINITY;
                if (col + 1 > row1) s4[nt][3] = -INFINITY;
            }
        }

        // partial row max over this warp's 32 cols
        float pm0 = fmaxf(fmaxf(s4[0][0], s4[0][1]), fmaxf(s4[1][0], s4[1][1]));
        pm0 = fmaxf(pm0, fmaxf(fmaxf(s4[2][0], s4[2][1]), fmaxf(s4[3][0], s4[3][1])));
        float pm1 = fmaxf(fmaxf(s4[0][2], s4[0][3]), fmaxf(s4[1][2], s4[1][3]));
        pm1 = fmaxf(pm1, fmaxf(fmaxf(s4[2][2], s4[2][3]), fmaxf(s4[3][2], s4[3][3])));
        pm0 = fmaxf(pm0, __shfl_xor_sync(0xffffffffu, pm0, 1));
        pm0 = fmaxf(pm0, __shfl_xor_sync(0xffffffffu, pm0, 2));
        pm1 = fmaxf(pm1, __shfl_xor_sync(0xffffffffu, pm1, 1));
        pm1 = fmaxf(pm1, __shfl_xor_sync(0xffffffffu, pm1, 2));
        if (q == 0) {
            pmax[wn * 64 + rbase]     = pm0;
            pmax[wn * 64 + rbase + 8] = pm1;
        }
        __syncthreads();

        if (t < 64) {
            float mo = mrow[t];
            float mn = fmaxf(mo, fmaxf(pmax[t], pmax[64 + t]));
            arow[t] = __expf(mo - mn);
            mrow[t] = mn;
        }
        __syncthreads();

        // P = exp(S - m), write to Ps (interleaved), partial sums, rescale O
        {
            const float mn0 = mrow[rbase], mn1 = mrow[rbase + 8];
            const float al0 = arow[rbase], al1 = arow[rbase + 8];
            float sum0 = 0.f, sum1 = 0.f;
            const int pos0 = ((2 * q) & 3) * 2 + ((2 * q) >> 2);
            const int pos1 = ((2 * q + 1) & 3) * 2 + ((2 * q + 1) >> 2);
            uint32_t* Pr0 = (uint32_t*)&Ps[rbase * 72];
            uint32_t* Pr1 = (uint32_t*)&Ps[(rbase + 8) * 72];
            #pragma unroll
            for (int nt = 0; nt < 4; nt++) {
                const int cb = wn * 32 + nt * 8;
                float p0 = __expf(s4[nt][0] - mn0), p1 = __expf(s4[nt][1] - mn0);
                float p2 = __expf(s4[nt][2] - mn1), p3 = __expf(s4[nt][3] - mn1);
                sum0 += p0 + p1; sum1 += p2 + p3;
                Pr0[cb + pos0] = f2tf(p0); Pr0[cb + pos1] = f2tf(p1);
                Pr1[cb + pos0] = f2tf(p2); Pr1[cb + pos1] = f2tf(p3);
                o[nt][0] *= al0; o[nt][1] *= al0; o[nt][2] *= al1; o[nt][3] *= al1;
            }
            sum0 += __shfl_xor_sync(0xffffffffu, sum0, 1);
            sum0 += __shfl_xor_sync(0xffffffffu, sum0, 2);
            sum1 += __shfl_xor_sync(0xffffffffu, sum1, 1);
            sum1 += __shfl_xor_sync(0xffffffffu, sum1, 2);
            if (q == 0) {
                psum[wn * 64 + rbase]     = sum0;
                psum[wn * 64 + rbase + 8] = sum1;
            }
        }
        __syncthreads();
        if (t < 64) lrw[t] = lrw[t] * arow[t] + psum[t] + psum[64 + t];

        // O += P V
        #pragma unroll
        for (int ks = 0; ks < 8; ks++) {
            uint2 alo = *(const uint2*)&Ps[aoff + ks * 8];
            uint2 ahi = *(const uint2*)&Ps[aoff + 8 * 72 + ks * 8];
            #pragma unroll
            for (int nt = 0; nt < 4; nt++) {
                uint2 b = *(const uint2*)&Vt[(wn * 32 + nt * 8 + g) * 72 + ks * 8 + 2 * q];
                mma8(o[nt], alo.x, ahi.x, alo.y, ahi.y, b.x, b.y);
            }
        }
    }
    __syncthreads();

    // Epilogue: normalize + write ctx [b][s][D]
    const int b = bh / HH, h = bh % HH;
    const float inv0 = 1.0f / lrw[rbase];
    const float inv1 = 1.0f / lrw[rbase + 8];
    const int s0 = qt * 64 + rbase, s1 = s0 + 8;
    float* C0 = g_ctx + ((size_t)b * SS + s0) * DD + h * HD;
    float* C1 = g_ctx + ((size_t)b * SS + s1) * DD + h * HD;
    #pragma unroll
    for (int nt = 0; nt < 4; nt++) {
        const int cc = wn * 32 + nt * 8 + 2 * q;
        *(float2*)(C0 + cc) = make_float2(o[nt][0] * inv0, o[nt][1] * inv0);
        *(float2*)(C1 + cc) = make_float2(o[nt][2] * inv1, o[nt][3] * inv1);
    }
}

// ---------------------------------------------------------------------------
extern "C" void kernel_launch(void* const* d_in, const int* in_sizes, int n_in,
                              void* d_out, int out_size)
{
    const float* x  = (const float*)d_in[0];
    const float* wq = (const float*)d_in[1];
    const float* wk = (const float*)d_in[2];
    const float* wv = (const float*)d_in[3];
    const float* wo = (const float*)d_in[4];
    const float* bo = (const float*)d_in[5];
    float* out = (float*)d_out;

    cudaFuncSetAttribute(attn_tc,
                         cudaFuncAttributeMaxDynamicSharedMemorySize,
                         ATTN_SMEM_BYTES);

    dim3 blk(256);
    dim3 gproj(DD / 128, (BB * SS) / 128);   // (6, 64)

    gemm_tc<<<gproj, blk>>>(x, wq, nullptr, nullptr, 1);
    gemm_tc<<<gproj, blk>>>(x, wk, nullptr, nullptr, 2);
    gemm_tc<<<gproj, blk>>>(x, wv, nullptr, nullptr, 3);

    attn_tc<<<dim3(SS / 64, BB * HH), blk, ATTN_SMEM_BYTES>>>();

    gemm_tc<<<gproj, blk>>>(nullptr, wo, bo, out, 0);
}

// round 7
// speedup vs baseline: 3.2992x; 1.1312x over previous
#include <cuda_runtime.h>
#include <math.h>
#include <stdint.h>

#define BB 4
#define SS 2048
#define DD 768
#define HH 12
#define HD 64

// Scratch
__device__ float g_q  [BB*HH*SS*HD];   // [bh][s][d]
__device__ float g_k  [BB*HH*SS*HD];   // [bh][s][d]
__device__ float g_vt [BB*HH*HD*SS];   // [bh][d][s]  (transposed V)
__device__ float g_ctx[BB*SS*DD];      // [b][s][D]

__device__ __forceinline__ uint32_t f2tf(float x) {
    uint32_t u; asm("cvt.rna.tf32.f32 %0, %1;" : "=r"(u) : "f"(x)); return u;
}

// D += A(16x8,row) * B(8x8,col), tf32 in, f32 accum
__device__ __forceinline__ void mma8(float* c, uint32_t a0, uint32_t a1,
                                     uint32_t a2, uint32_t a3,
                                     uint32_t b0, uint32_t b1) {
    asm volatile(
        "mma.sync.aligned.m16n8k8.row.col.f32.tf32.tf32.f32 "
        "{%0,%1,%2,%3}, {%4,%5,%6,%7}, {%8,%9}, {%0,%1,%2,%3};"
        : "+f"(c[0]), "+f"(c[1]), "+f"(c[2]), "+f"(c[3])
        : "r"(a0), "r"(a1), "r"(a2), "r"(a3), "r"(b0), "r"(b1));
}

// ---------------------------------------------------------------------------
// TF32 GEMM: C[M,N] = A[M,K] @ W[N,K]^T.  M=8192, N=768, K=768.
// Block 128x128, BK=16, 256 threads = 8 warps (2m x 4n), warp tile 64x32.
// Double-buffered smem: ONE __syncthreads per K-slab.
// mode: 0 = out-proj (A=g_ctx, +bias -> out)
//       1/2 = Q/K proj -> g_q/g_k [bh][s][d]
//       3 = V proj -> g_vt [bh][d][s]   (transposed epilogue)
// ---------------------------------------------------------------------------
__global__ __launch_bounds__(256) void gemm_tc(
    const float* __restrict__ A, const float* __restrict__ W,
    const float* __restrict__ bias, float* __restrict__ out, int mode)
{
    __shared__ uint32_t As[2][128*24];
    __shared__ uint32_t Bs[2][128*24];

    const int t = threadIdx.x;
    const int lane = t & 31;
    const int q = lane & 3, g = lane >> 2;
    const int warp = t >> 5;
    const int wm = warp & 1, wn = warp >> 1;
    const int m0 = blockIdx.y * 128, n0 = blockIdx.x * 128;

    const int lrow = t >> 2;            // 0..63
    const int lc4  = (t & 3) * 4;       // 0,4,8,12
    const int sb   = (lc4 & 8) + ((lc4 >> 2) & 1);  // interleaved col base

    const float* Ap = (mode == 0) ? (const float*)g_ctx : A;
    const float* Ag0 = Ap + (size_t)(m0 + lrow) * DD + lc4;
    const float* Ag1 = Ag0 + (size_t)64 * DD;
    const float* Wg0 = W + (size_t)(n0 + lrow) * DD + lc4;
    const float* Wg1 = Wg0 + (size_t)64 * DD;

    float c[4][4][4] = {};

    float4 pa0 = *(const float4*)Ag0;
    float4 pa1 = *(const float4*)Ag1;
    float4 pb0 = *(const float4*)Wg0;
    float4 pb1 = *(const float4*)Wg1;

    // stage slab 0 into buffer 0
    {
        uint32_t* d0 = &As[0][lrow * 24 + sb];
        d0[0] = f2tf(pa0.x); d0[2] = f2tf(pa0.y); d0[4] = f2tf(pa0.z); d0[6] = f2tf(pa0.w);
        uint32_t* d1 = &As[0][(lrow + 64) * 24 + sb];
        d1[0] = f2tf(pa1.x); d1[2] = f2tf(pa1.y); d1[4] = f2tf(pa1.z); d1[6] = f2tf(pa1.w);
        uint32_t* d2 = &Bs[0][lrow * 24 + sb];
        d2[0] = f2tf(pb0.x); d2[2] = f2tf(pb0.y); d2[4] = f2tf(pb0.z); d2[6] = f2tf(pb0.w);
        uint32_t* d3 = &Bs[0][(lrow + 64) * 24 + sb];
        d3[0] = f2tf(pb1.x); d3[2] = f2tf(pb1.y); d3[4] = f2tf(pb1.z); d3[6] = f2tf(pb1.w);
    }
    __syncthreads();

    const int NIT = DD / 16;   // 48
    for (int it = 0; it < NIT; it++) {
        const int cur = it & 1;
        if (it + 1 < NIT) {
            const int k0 = (it + 1) * 16;
            pa0 = *(const float4*)(Ag0 + k0);
            pa1 = *(const float4*)(Ag1 + k0);
            pb0 = *(const float4*)(Wg0 + k0);
            pb1 = *(const float4*)(Wg1 + k0);
        }

        #pragma unroll
        for (int ks = 0; ks < 2; ks++) {
            uint2 a[4][2]; uint2 b[4];
            #pragma unroll
            for (int mt = 0; mt < 4; mt++) {
                int r = wm * 64 + mt * 16 + g;
                a[mt][0] = *(const uint2*)&As[cur][r * 24 + ks * 8 + 2 * q];
                a[mt][1] = *(const uint2*)&As[cur][(r + 8) * 24 + ks * 8 + 2 * q];
            }
            #pragma unroll
            for (int nt = 0; nt < 4; nt++) {
                int r = wn * 32 + nt * 8 + g;
                b[nt] = *(const uint2*)&Bs[cur][r * 24 + ks * 8 + 2 * q];
            }
            #pragma unroll
            for (int mt = 0; mt < 4; mt++)
                #pragma unroll
                for (int nt = 0; nt < 4; nt++)
                    mma8(c[mt][nt], a[mt][0].x, a[mt][1].x, a[mt][0].y, a[mt][1].y,
                         b[nt].x, b[nt].y);
        }

        if (it + 1 < NIT) {
            const int nxt = cur ^ 1;
            uint32_t* d0 = &As[nxt][lrow * 24 + sb];
            d0[0] = f2tf(pa0.x); d0[2] = f2tf(pa0.y); d0[4] = f2tf(pa0.z); d0[6] = f2tf(pa0.w);
            uint32_t* d1 = &As[nxt][(lrow + 64) * 24 + sb];
            d1[0] = f2tf(pa1.x); d1[2] = f2tf(pa1.y); d1[4] = f2tf(pa1.z); d1[6] = f2tf(pa1.w);
            uint32_t* d2 = &Bs[nxt][lrow * 24 + sb];
            d2[0] = f2tf(pb0.x); d2[2] = f2tf(pb0.y); d2[4] = f2tf(pb0.z); d2[6] = f2tf(pb0.w);
            uint32_t* d3 = &Bs[nxt][(lrow + 64) * 24 + sb];
            d3[0] = f2tf(pb1.x); d3[2] = f2tf(pb1.y); d3[4] = f2tf(pb1.z); d3[6] = f2tf(pb1.w);
            __syncthreads();
        }
    }

    // Epilogue
    #pragma unroll
    for (int mt = 0; mt < 4; mt++) {
        const int r0 = m0 + wm * 64 + mt * 16 + g;   // r1 = r0+8, same batch
        #pragma unroll
        for (int nt = 0; nt < 4; nt++) {
            const int cc = n0 + wn * 32 + nt * 8 + 2 * q;
            if (mode == 0) {
                float2 bv = *(const float2*)(bias + cc);
                *(float2*)(out + (size_t)r0 * DD + cc) =
                    make_float2(c[mt][nt][0] + bv.x, c[mt][nt][1] + bv.y);
                *(float2*)(out + (size_t)(r0 + 8) * DD + cc) =
                    make_float2(c[mt][nt][2] + bv.x, c[mt][nt][3] + bv.y);
            } else {
                const int h = cc >> 6, d = cc & 63;
                const int bi = r0 >> 11, s0 = r0 & (SS - 1), s1 = s0 + 8;
                if (mode == 3) {
                    float* dst = g_vt + ((size_t)((bi * HH + h) * HD + d)) * SS;
                    dst[s0]      = c[mt][nt][0];
                    dst[SS + s0] = c[mt][nt][1];
                    dst[s1]      = c[mt][nt][2];
                    dst[SS + s1] = c[mt][nt][3];
                } else {
                    float* dst = (mode == 1) ? g_q : g_k;
                    *(float2*)(dst + ((size_t)(bi * HH + h) * SS + s0) * HD + d) =
                        make_float2(c[mt][nt][0], c[mt][nt][1]);
                    *(float2*)(dst + ((size_t)(bi * HH + h) * SS + s1) * HD + d) =
                        make_float2(c[mt][nt][2], c[mt][nt][3]);
                }
            }
        }
    }
}

// ---------------------------------------------------------------------------
// TF32 flash attention v2, causal. Block = 128 q-rows x 64 kv tile.
// 8 warps; warp w owns q-rows 16w..16w+15 and ALL 64 kv columns
//  -> softmax entirely warp-local (registers + quad shuffles, no smem stats).
// Q fragments persistent in registers. P round-trip via warp-private smem.
// ---------------------------------------------------------------------------
#define ATTN_SMEM_BYTES (18432 * 4)   // Ks 64x72 + Vt 64x72 + Ps 128x72

__global__ __launch_bounds__(256) void attn_tc2()
{
    extern __shared__ float sm[];
    float* Ks = sm;                 // [64 n][72]
    float* Vt = sm + 4608;          // [64 d][72]
    float* Ps = sm + 9216;          // [128 r][72]  (Q staging, then P per warp)

    const int t = threadIdx.x;
    const int lane = t & 31;
    const int q = lane & 3, g = lane >> 2;
    const int w = t >> 5;
    const int qtb = gridDim.x - 1 - blockIdx.x;   // heavy blocks first
    const int bh = blockIdx.y;

    const int d4 = (t & 15) * 4;
    const int rb = t >> 4;                        // 0..15
    const int sb = (d4 >> 3) * 8 + ((d4 >> 2) & 1);

    const float* Qg = g_q  + ((size_t)bh * SS + qtb * 128) * HD;
    const float* Kg = g_k  + (size_t)bh * SS * HD;
    const float* Vg = g_vt + (size_t)bh * HD * SS;

    // Stage Q (pre-scaled by 1/8) into Ps, interleaved tf32
    #pragma unroll
    for (int i = 0; i < 8; i++) {
        int r = rb + 16 * i;
        float4 v = *(const float4*)(Qg + r * HD + d4);
        uint32_t* dst = (uint32_t*)&Ps[r * 72 + sb];
        dst[0] = f2tf(v.x * 0.125f); dst[2] = f2tf(v.y * 0.125f);
        dst[4] = f2tf(v.z * 0.125f); dst[6] = f2tf(v.w * 0.125f);
    }
    __syncthreads();

    // Q fragments -> registers (persistent)
    uint32_t qa[8][4];
    {
        const uint32_t* P0 = (const uint32_t*)&Ps[(16 * w + g) * 72 + 2 * q];
        const uint32_t* P1 = (const uint32_t*)&Ps[(16 * w + g + 8) * 72 + 2 * q];
        #pragma unroll
        for (int ks = 0; ks < 8; ks++) {
            uint2 lo = *(const uint2*)&P0[ks * 8];
            uint2 hi = *(const uint2*)&P1[ks * 8];
            qa[ks][0] = lo.x; qa[ks][1] = hi.x; qa[ks][2] = lo.y; qa[ks][3] = hi.y;
        }
    }

    float o[8][4] = {};
    float m0 = -INFINITY, m1 = -INFINITY, l0 = 0.f, l1 = 0.f;

    const int row0g = 128 * qtb + 16 * w + g;
    const int row1g = row0g + 8;
    const int ntiles = 2 * qtb + 2;

    uint32_t* Pr0 = (uint32_t*)&Ps[(16 * w + g) * 72];
    uint32_t* Pr1 = (uint32_t*)&Ps[(16 * w + g + 8) * 72];
    const int pos0 = ((2 * q) & 3) * 2 + ((2 * q) >> 2);
    const int pos1 = ((2 * q + 1) & 3) * 2 + ((2 * q + 1) >> 2);

    for (int kt = 0; kt < ntiles; kt++) {
        __syncthreads();   // previous tile's K/V readers done
        #pragma unroll
        for (int i = 0; i < 4; i++) {
            int r = rb + 16 * i;
            float4 v = *(const float4*)(Kg + (size_t)(64 * kt + r) * HD + d4);
            uint32_t* dst = (uint32_t*)&Ks[r * 72 + sb];
            dst[0] = f2tf(v.x); dst[2] = f2tf(v.y);
            dst[4] = f2tf(v.z); dst[6] = f2tf(v.w);
        }
        #pragma unroll
        for (int i = 0; i < 4; i++) {
            int d = rb + 16 * i;
            float4 v = *(const float4*)(Vg + (size_t)d * SS + 64 * kt + d4);
            uint32_t* dst = (uint32_t*)&Vt[d * 72 + sb];
            dst[0] = f2tf(v.x); dst[2] = f2tf(v.y);
            dst[4] = f2tf(v.z); dst[6] = f2tf(v.w);
        }
        __syncthreads();

        // tile entirely above this warp's rows -> no work (loads already done)
        if (64 * kt > 128 * qtb + 16 * w + 15) continue;

        // ---- S = Q K^T : warp computes 16 x 64 ----
        float s4[8][4];
        #pragma unroll
        for (int nt = 0; nt < 8; nt++) {
            s4[nt][0] = 0.f; s4[nt][1] = 0.f; s4[nt][2] = 0.f; s4[nt][3] = 0.f;
        }
        #pragma unroll
        for (int ks = 0; ks < 8; ks++) {
            #pragma unroll
            for (int nt = 0; nt < 8; nt++) {
                uint2 b = *(const uint2*)&Ks[(8 * nt + g) * 72 + ks * 8 + 2 * q];
                mma8(s4[nt], qa[ks][0], qa[ks][1], qa[ks][2], qa[ks][3], b.x, b.y);
            }
        }

        // causal mask (only when the tile straddles the diagonal for this warp)
        if (64 * kt + 63 > 128 * qtb + 16 * w) {
            #pragma unroll
            for (int nt = 0; nt < 8; nt++) {
                int colg = 64 * kt + 8 * nt + 2 * q;
                if (colg     > row0g) s4[nt][0] = -INFINITY;
                if (colg + 1 > row0g) s4[nt][1] = -INFINITY;
                if (colg     > row1g) s4[nt][2] = -INFINITY;
                if (colg + 1 > row1g) s4[nt][3] = -INFINITY;
            }
        }

        // ---- warp-local online softmax ----
        float pm0 = -INFINITY, pm1 = -INFINITY;
        #pragma unroll
        for (int nt = 0; nt < 8; nt++) {
            pm0 = fmaxf(pm0, fmaxf(s4[nt][0], s4[nt][1]));
            pm1 = fmaxf(pm1, fmaxf(s4[nt][2], s4[nt][3]));
        }
        pm0 = fmaxf(pm0, __shfl_xor_sync(0xffffffffu, pm0, 1));
        pm0 = fmaxf(pm0, __shfl_xor_sync(0xffffffffu, pm0, 2));
        pm1 = fmaxf(pm1, __shfl_xor_sync(0xffffffffu, pm1, 1));
        pm1 = fmaxf(pm1, __shfl_xor_sync(0xffffffffu, pm1, 2));

        const float mn0 = fmaxf(m0, pm0), mn1 = fmaxf(m1, pm1);
        const float al0 = __expf(m0 - mn0), al1 = __expf(m1 - mn1);
        m0 = mn0; m1 = mn1;

        float sum0 = 0.f, sum1 = 0.f;
        #pragma unroll
        for (int nt = 0; nt < 8; nt++) {
            float p0 = __expf(s4[nt][0] - mn0), p1 = __expf(s4[nt][1] - mn0);
            float p2 = __expf(s4[nt][2] - mn1), p3 = __expf(s4[nt][3] - mn1);
            sum0 += p0 + p1; sum1 += p2 + p3;
            Pr0[8 * nt + pos0] = f2tf(p0); Pr0[8 * nt + pos1] = f2tf(p1);
            Pr1[8 * nt + pos0] = f2tf(p2); Pr1[8 * nt + pos1] = f2tf(p3);
        }
        sum0 += __shfl_xor_sync(0xffffffffu, sum0, 1);
        sum0 += __shfl_xor_sync(0xffffffffu, sum0, 2);
        sum1 += __shfl_xor_sync(0xffffffffu, sum1, 1);
        sum1 += __shfl_xor_sync(0xffffffffu, sum1, 2);
        l0 = l0 * al0 + sum0;
        l1 = l1 * al1 + sum1;

        #pragma unroll
        for (int nd = 0; nd < 8; nd++) {
            o[nd][0] *= al0; o[nd][1] *= al0; o[nd][2] *= al1; o[nd][3] *= al1;
        }
        __syncwarp();   // P stores visible to quad-mates before fragment reads

        // ---- O += P V ----
        #pragma unroll
        for (int ks = 0; ks < 8; ks++) {
            uint2 lo = *(const uint2*)&Pr0[ks * 8 + 2 * q];
            uint2 hi = *(const uint2*)&Pr1[ks * 8 + 2 * q];
            #pragma unroll
            for (int nd = 0; nd < 8; nd++) {
                uint2 b = *(const uint2*)&Vt[(8 * nd + g) * 72 + ks * 8 + 2 * q];
                mma8(o[nd], lo.x, hi.x, lo.y, hi.y, b.x, b.y);
            }
        }
        __syncwarp();   // fragment reads done before next tile's P stores
    }

    // ---- epilogue: normalize, write ctx [b][s][D] ----
    const float inv0 = 1.0f / l0, inv1 = 1.0f / l1;
    const int b = bh / HH, h = bh % HH;
    const int s0 = 128 * qtb + 16 * w + g, s1 = s0 + 8;
    float* C0 = g_ctx + ((size_t)b * SS + s0) * DD + h * HD;
    float* C1 = g_ctx + ((size_t)b * SS + s1) * DD + h * HD;
    #pragma unroll
    for (int nd = 0; nd < 8; nd++) {
        int cc = 8 * nd + 2 * q;
        *(float2*)(C0 + cc) = make_float2(o[nd][0] * inv0, o[nd][1] * inv0);
        *(float2*)(C1 + cc) = make_float2(o[nd][2] * inv1, o[nd][3] * inv1);
    }
}

// ---------------------------------------------------------------------------
extern "C" void kernel_launch(void* const* d_in, const int* in_sizes, int n_in,
                              void* d_out, int out_size)
{
    const float* x  = (const float*)d_in[0];
    const float* wq = (const float*)d_in[1];
    const float* wk = (const float*)d_in[2];
    const float* wv = (const float*)d_in[3];
    const float* wo = (const float*)d_in[4];
    const float* bo = (const float*)d_in[5];
    float* out = (float*)d_out;

    cudaFuncSetAttribute(attn_tc2,
                         cudaFuncAttributeMaxDynamicSharedMemorySize,
                         ATTN_SMEM_BYTES);

    dim3 blk(256);
    dim3 gproj(DD / 128, (BB * SS) / 128);   // (6, 64)

    gemm_tc<<<gproj, blk>>>(x, wq, nullptr, nullptr, 1);
    gemm_tc<<<gproj, blk>>>(x, wk, nullptr, nullptr, 2);
    gemm_tc<<<gproj, blk>>>(x, wv, nullptr, nullptr, 3);

    attn_tc2<<<dim3(SS / 128, BB * HH), blk, ATTN_SMEM_BYTES>>>();

    gemm_tc<<<gproj, blk>>>(nullptr, wo, bo, out, 0);
}

// round 8
// speedup vs baseline: 4.6060x; 1.3961x over previous
#include <cuda_runtime.h>
#include <cuda_fp16.h>
#include <math.h>
#include <stdint.h>

#define BB 4
#define SS 2048
#define DD 768
#define HH 12
#define HD 64

// Scratch: q/k/vt in half (written by projection epilogues), ctx f32
__device__ __half g_q  [BB*HH*SS*HD];   // [bh][s][d]   (pre-scaled by 0.125)
__device__ __half g_k  [BB*HH*SS*HD];   // [bh][s][d]
__device__ __half g_vt [BB*HH*HD*SS];   // [bh][d][s]   (transposed V)
__device__ float  g_ctx[BB*SS*DD];      // [b][s][D]

// D += A(16x16,row) * B(16x8,col), f16 in, f32 accum
__device__ __forceinline__ void mma16(float* c, uint32_t a0, uint32_t a1,
                                      uint32_t a2, uint32_t a3,
                                      uint32_t b0, uint32_t b1) {
    asm volatile(
        "mma.sync.aligned.m16n8k16.row.col.f32.f16.f16.f32 "
        "{%0,%1,%2,%3}, {%4,%5,%6,%7}, {%8,%9}, {%0,%1,%2,%3};"
        : "+f"(c[0]), "+f"(c[1]), "+f"(c[2]), "+f"(c[3])
        : "r"(a0), "r"(a1), "r"(a2), "r"(a3), "r"(b0), "r"(b1));
}
__device__ __forceinline__ void ldmx4(uint32_t* r, uint32_t addr) {
    asm volatile("ldmatrix.sync.aligned.m8n8.x4.shared.b16 {%0,%1,%2,%3}, [%4];"
        : "=r"(r[0]), "=r"(r[1]), "=r"(r[2]), "=r"(r[3]) : "r"(addr));
}
__device__ __forceinline__ void ldmx2(uint32_t* r, uint32_t addr) {
    asm volatile("ldmatrix.sync.aligned.m8n8.x2.shared.b16 {%0,%1}, [%2];"
        : "=r"(r[0]), "=r"(r[1]) : "r"(addr));
}

// ---------------------------------------------------------------------------
// FP16 GEMM: C[M,N] = A[M,K] @ W[N,K]^T.  M=8192, N=768, K=768.
// Block 128x128, BK=16, 256 thr = 8 warps (2m x 4n), warp tile 64x32.
// Smem half tiles, row stride 24 halves (48B) -> ldmatrix conflict-free.
// mode: 0 = out-proj (A=g_ctx, +bias -> f32 out)
//       1 = Q proj (scale 0.125 -> g_q half)   2 = K proj -> g_k half
//       3 = V proj -> g_vt half (transposed epilogue)
// ---------------------------------------------------------------------------
__global__ __launch_bounds__(256) void gemm_h(
    const float* __restrict__ A, const float* __restrict__ W,
    const float* __restrict__ bias, float* __restrict__ out, int mode)
{
    __shared__ __half As[2][128*24];
    __shared__ __half Bs[2][128*24];

    const int t = threadIdx.x;
    const int lane = t & 31;
    const int q = lane & 3, g = lane >> 2;
    const int warp = t >> 5;
    const int wm = warp & 1, wn = warp >> 1;
    const int m0 = blockIdx.y * 128, n0 = blockIdx.x * 128;

    const int arow = t >> 1;          // 0..127
    const int ac8  = (t & 1) * 8;     // 0 or 8

    const float* Ap = (mode == 0) ? (const float*)g_ctx : A;
    const float* Ag = Ap + (size_t)(m0 + arow) * DD + ac8;
    const float* Wg = W + (size_t)(n0 + arow) * DD + ac8;

    const uint32_t asb[2] = { (uint32_t)__cvta_generic_to_shared(As[0]),
                              (uint32_t)__cvta_generic_to_shared(As[1]) };
    const uint32_t bsb[2] = { (uint32_t)__cvta_generic_to_shared(Bs[0]),
                              (uint32_t)__cvta_generic_to_shared(Bs[1]) };

    // ldmatrix per-lane offsets (bytes); row stride = 24 halves = 48 B
    const int a4off = (((lane & 7) + ((lane >> 3) & 1) * 8) * 24 + (lane >> 4) * 8) * 2;
    const int b2off = ((lane & 7) * 24 + ((lane >> 3) & 1) * 8) * 2;

    float c[4][4][4] = {};

    float4 pa0 = *(const float4*)Ag;
    float4 pa1 = *(const float4*)(Ag + 4);
    float4 pb0 = *(const float4*)Wg;
    float4 pb1 = *(const float4*)(Wg + 4);

    {   // stage slab 0 -> buffer 0
        __half2* da = (__half2*)&As[0][arow * 24 + ac8];
        da[0] = __floats2half2_rn(pa0.x, pa0.y); da[1] = __floats2half2_rn(pa0.z, pa0.w);
        da[2] = __floats2half2_rn(pa1.x, pa1.y); da[3] = __floats2half2_rn(pa1.z, pa1.w);
        __half2* db = (__half2*)&Bs[0][arow * 24 + ac8];
        db[0] = __floats2half2_rn(pb0.x, pb0.y); db[1] = __floats2half2_rn(pb0.z, pb0.w);
        db[2] = __floats2half2_rn(pb1.x, pb1.y); db[3] = __floats2half2_rn(pb1.z, pb1.w);
    }
    __syncthreads();

    const int NIT = DD / 16;   // 48
    for (int it = 0; it < NIT; it++) {
        const int cur = it & 1;
        if (it + 1 < NIT) {
            const int k0 = (it + 1) * 16;
            pa0 = *(const float4*)(Ag + k0);
            pa1 = *(const float4*)(Ag + k0 + 4);
            pb0 = *(const float4*)(Wg + k0);
            pb1 = *(const float4*)(Wg + k0 + 4);
        }

        uint32_t a[4][4]; uint32_t b[4][2];
        #pragma unroll
        for (int mt = 0; mt < 4; mt++)
            ldmx4(a[mt], asb[cur] + (wm * 64 + mt * 16) * 48 + a4off);
        #pragma unroll
        for (int nt = 0; nt < 4; nt++)
            ldmx2(b[nt], bsb[cur] + (wn * 32 + nt * 8) * 48 + b2off);
        #pragma unroll
        for (int mt = 0; mt < 4; mt++)
            #pragma unroll
            for (int nt = 0; nt < 4; nt++)
                mma16(c[mt][nt], a[mt][0], a[mt][1], a[mt][2], a[mt][3],
                      b[nt][0], b[nt][1]);

        if (it + 1 < NIT) {
            const int nxt = cur ^ 1;
            __half2* da = (__half2*)&As[nxt][arow * 24 + ac8];
            da[0] = __floats2half2_rn(pa0.x, pa0.y); da[1] = __floats2half2_rn(pa0.z, pa0.w);
            da[2] = __floats2half2_rn(pa1.x, pa1.y); da[3] = __floats2half2_rn(pa1.z, pa1.w);
            __half2* db = (__half2*)&Bs[nxt][arow * 24 + ac8];
            db[0] = __floats2half2_rn(pb0.x, pb0.y); db[1] = __floats2half2_rn(pb0.z, pb0.w);
            db[2] = __floats2half2_rn(pb1.x, pb1.y); db[3] = __floats2half2_rn(pb1.z, pb1.w);
            __syncthreads();
        }
    }

    // Epilogue
    #pragma unroll
    for (int mt = 0; mt < 4; mt++) {
        const int r0 = m0 + wm * 64 + mt * 16 + g;   // r1 = r0 + 8, same batch
        #pragma unroll
        for (int nt = 0; nt < 4; nt++) {
            const int cc = n0 + wn * 32 + nt * 8 + 2 * q;
            float* cf = c[mt][nt];
            if (mode == 0) {
                float2 bv = *(const float2*)(bias + cc);
                *(float2*)(out + (size_t)r0 * DD + cc) =
                    make_float2(cf[0] + bv.x, cf[1] + bv.y);
                *(float2*)(out + (size_t)(r0 + 8) * DD + cc) =
                    make_float2(cf[2] + bv.x, cf[3] + bv.y);
            } else {
                const int h = cc >> 6, d = cc & 63;
                const int bi = r0 >> 11, s0 = r0 & (SS - 1), s1 = s0 + 8;
                if (mode == 3) {
                    __half* dst = g_vt + ((size_t)((bi * HH + h) * HD + d)) * SS;
                    dst[s0]      = __float2half(cf[0]);
                    dst[SS + s0] = __float2half(cf[1]);
                    dst[s1]      = __float2half(cf[2]);
                    dst[SS + s1] = __float2half(cf[3]);
                } else {
                    const float sc = (mode == 1) ? 0.125f : 1.0f;
                    __half* dst = (mode == 1) ? g_q : g_k;
                    *(__half2*)(dst + ((size_t)(bi * HH + h) * SS + s0) * HD + d) =
                        __floats2half2_rn(cf[0] * sc, cf[1] * sc);
                    *(__half2*)(dst + ((size_t)(bi * HH + h) * SS + s1) * HD + d) =
                        __floats2half2_rn(cf[2] * sc, cf[3] * sc);
                }
            }
        }
    }
}

// ---------------------------------------------------------------------------
// FP16 flash attention, causal. Block = 128 q-rows x 64 kv tile, 8 warps;
// warp w owns q-rows 16w..16w+15, all 64 kv cols. Warp-local softmax.
// Fragments via ldmatrix; K/V tiles are raw uint4 copies (already half).
// ---------------------------------------------------------------------------
__global__ __launch_bounds__(256) void attn_h()
{
    __shared__ __half Ks[64 * 72];    // [n kv][72]
    __shared__ __half Vt[64 * 72];    // [d][72]
    __shared__ __half Ps[128 * 72];   // Q staging, then per-warp P

    const int t = threadIdx.x;
    const int lane = t & 31;
    const int q = lane & 3, g = lane >> 2;
    const int w = t >> 5;
    const int qtb = gridDim.x - 1 - blockIdx.x;   // heavy blocks first
    const int bh = blockIdx.y;

    const int krow = t & 63, kuq = t >> 6;        // K/V loader: 8-row quarters
    const int qrow = t & 127, quh = t >> 7;       // Q loader

    const uint32_t ks_b = (uint32_t)__cvta_generic_to_shared(Ks);
    const uint32_t vt_b = (uint32_t)__cvta_generic_to_shared(Vt);
    const uint32_t ps_b = (uint32_t)__cvta_generic_to_shared(Ps);

    // ldmatrix per-lane offsets (bytes); row stride = 72 halves = 144 B
    const int a4off = (((lane & 7) + ((lane >> 3) & 1) * 8) * 72 + (lane >> 4) * 8) * 2;
    const int b2off = ((lane & 7) * 72 + ((lane >> 3) & 1) * 8) * 2;

    // ---- stage Q (already half + pre-scaled) ----
    {
        const uint4* Qg = (const uint4*)(g_q + ((size_t)bh * SS + qtb * 128 + qrow) * HD);
        uint4* Pd = (uint4*)&Ps[qrow * 72];
        #pragma unroll
        for (int i = 0; i < 4; i++) {
            int c8 = quh + 2 * i;     // 0..7 across the two quh values
            Pd[c8] = Qg[c8];
        }
    }
    __syncthreads();

    // Q fragments -> registers (persistent): 4 k16 steps
    uint32_t qa[4][4];
    #pragma unroll
    for (int ks = 0; ks < 4; ks++)
        ldmx4(qa[ks], ps_b + w * 16 * 144 + a4off + ks * 32);

    float o[8][4] = {};
    float m0 = -INFINITY, m1 = -INFINITY, l0 = 0.f, l1 = 0.f;

    const int row0g = 128 * qtb + 16 * w + g;
    const int row1g = row0g + 8;
    const int ntiles = 2 * qtb + 2;

    __half2* Pr0 = (__half2*)&Ps[(16 * w + g) * 72];
    __half2* Pr1 = (__half2*)&Ps[(16 * w + g + 8) * 72];

    for (int kt = 0; kt < ntiles; kt++) {
        __syncthreads();   // previous tile's readers done
        {
            const uint4* Kg = (const uint4*)(g_k + ((size_t)bh * SS + 64 * kt + krow) * HD);
            uint4* Kd = (uint4*)&Ks[krow * 72];
            Kd[kuq]     = Kg[kuq];
            Kd[kuq + 4] = Kg[kuq + 4];
            const uint4* Vgp = (const uint4*)(g_vt + ((size_t)bh * HD + krow) * SS + 64 * kt);
            uint4* Vd = (uint4*)&Vt[krow * 72];
            Vd[kuq]     = Vgp[kuq];
            Vd[kuq + 4] = Vgp[kuq + 4];
        }
        __syncthreads();

        // tile entirely above this warp's rows -> nothing to do
        if (64 * kt > 128 * qtb + 16 * w + 15) continue;

        // ---- S = Q K^T : 16 x 64 per warp ----
        float s4[8][4] = {};
        #pragma unroll
        for (int ks = 0; ks < 4; ks++) {
            #pragma unroll
            for (int nt = 0; nt < 8; nt++) {
                uint32_t b[2];
                ldmx2(b, ks_b + nt * 8 * 144 + b2off + ks * 32);
                mma16(s4[nt], qa[ks][0], qa[ks][1], qa[ks][2], qa[ks][3], b[0], b[1]);
            }
        }

        // causal mask on straddling tiles
        if (64 * kt + 63 > 128 * qtb + 16 * w) {
            #pragma unroll
            for (int nt = 0; nt < 8; nt++) {
                int colg = 64 * kt + 8 * nt + 2 * q;
                if (colg     > row0g) s4[nt][0] = -INFINITY;
                if (colg + 1 > row0g) s4[nt][1] = -INFINITY;
                if (colg     > row1g) s4[nt][2] = -INFINITY;
                if (colg + 1 > row1g) s4[nt][3] = -INFINITY;
            }
        }

        // ---- warp-local online softmax ----
        float pm0 = -INFINITY, pm1 = -INFINITY;
        #pragma unroll
        for (int nt = 0; nt < 8; nt++) {
            pm0 = fmaxf(pm0, fmaxf(s4[nt][0], s4[nt][1]));
            pm1 = fmaxf(pm1, fmaxf(s4[nt][2], s4[nt][3]));
        }
        pm0 = fmaxf(pm0, __shfl_xor_sync(0xffffffffu, pm0, 1));
        pm0 = fmaxf(pm0, __shfl_xor_sync(0xffffffffu, pm0, 2));
        pm1 = fmaxf(pm1, __shfl_xor_sync(0xffffffffu, pm1, 1));
        pm1 = fmaxf(pm1, __shfl_xor_sync(0xffffffffu, pm1, 2));

        const float mn0 = fmaxf(m0, pm0), mn1 = fmaxf(m1, pm1);
        const float al0 = __expf(m0 - mn0), al1 = __expf(m1 - mn1);
        m0 = mn0; m1 = mn1;

        float sum0 = 0.f, sum1 = 0.f;
        #pragma unroll
        for (int nt = 0; nt < 8; nt++) {
            float p0 = __expf(s4[nt][0] - mn0), p1 = __expf(s4[nt][1] - mn0);
            float p2 = __expf(s4[nt][2] - mn1), p3 = __expf(s4[nt][3] - mn1);
            sum0 += p0 + p1; sum1 += p2 + p3;
            Pr0[4 * nt + q] = __floats2half2_rn(p0, p1);
            Pr1[4 * nt + q] = __floats2half2_rn(p2, p3);
        }
        sum0 += __shfl_xor_sync(0xffffffffu, sum0, 1);
        sum0 += __shfl_xor_sync(0xffffffffu, sum0, 2);
        sum1 += __shfl_xor_sync(0xffffffffu, sum1, 1);
        sum1 += __shfl_xor_sync(0xffffffffu, sum1, 2);
        l0 = l0 * al0 + sum0;
        l1 = l1 * al1 + sum1;

        #pragma unroll
        for (int nd = 0; nd < 8; nd++) {
            o[nd][0] *= al0; o[nd][1] *= al0; o[nd][2] *= al1; o[nd][3] *= al1;
        }
        __syncwarp();   // P stores visible before ldmatrix reads

        // ---- O += P V ----
        uint32_t pf[4][4];
        #pragma unroll
        for (int ks = 0; ks < 4; ks++)
            ldmx4(pf[ks], ps_b + w * 16 * 144 + a4off + ks * 32);
        #pragma unroll
        for (int ks = 0; ks < 4; ks++) {
            #pragma unroll
            for (int nd = 0; nd < 8; nd++) {
                uint32_t b[2];
                ldmx2(b, vt_b + nd * 8 * 144 + b2off + ks * 32);
                mma16(o[nd], pf[ks][0], pf[ks][1], pf[ks][2], pf[ks][3], b[0], b[1]);
            }
        }
        __syncwarp();   // reads done before next tile's P stores
    }

    // ---- epilogue: normalize, write ctx [b][s][D] (f32) ----
    const float inv0 = 1.0f / l0, inv1 = 1.0f / l1;
    const int b = bh / HH, h = bh % HH;
    const int s0 = 128 * qtb + 16 * w + g, s1 = s0 + 8;
    float* C0 = g_ctx + ((size_t)b * SS + s0) * DD + h * HD;
    float* C1 = g_ctx + ((size_t)b * SS + s1) * DD + h * HD;
    #pragma unroll
    for (int nd = 0; nd < 8; nd++) {
        int cc = 8 * nd + 2 * q;
        *(float2*)(C0 + cc) = make_float2(o[nd][0] * inv0, o[nd][1] * inv0);
        *(float2*)(C1 + cc) = make_float2(o[nd][2] * inv1, o[nd][3] * inv1);
    }
}

// ---------------------------------------------------------------------------
extern "C" void kernel_launch(void* const* d_in, const int* in_sizes, int n_in,
                              void* d_out, int out_size)
{
    const float* x  = (const float*)d_in[0];
    const float* wq = (const float*)d_in[1];
    const float* wk = (const float*)d_in[2];
    const float* wv = (const float*)d_in[3];
    const float* wo = (const float*)d_in[4];
    const float* bo = (const float*)d_in[5];
    float* out = (float*)d_out;

    dim3 blk(256);
    dim3 gproj(DD / 128, (BB * SS) / 128);   // (6, 64)

    gemm_h<<<gproj, blk>>>(x, wq, nullptr, nullptr, 1);
    gemm_h<<<gproj, blk>>>(x, wk, nullptr, nullptr, 2);
    gemm_h<<<gproj, blk>>>(x, wv, nullptr, nullptr, 3);

    attn_h<<<dim3(SS / 128, BB * HH), blk>>>();

    gemm_h<<<gproj, blk>>>(nullptr, wo, bo, out, 0);
}

// round 9
// speedup vs baseline: 5.9745x; 1.2971x over previous
#include <cuda_runtime.h>
#include <cuda_fp16.h>
#include <math.h>
#include <stdint.h>

#define BB 4
#define SS 2048
#define DD 768
#define HH 12
#define HD 64

// half scratch
__device__ __half g_xh [BB*SS*DD];      // x in half
__device__ __half g_wqh[DD*DD];
__device__ __half g_wkh[DD*DD];
__device__ __half g_wvh[DD*DD];
__device__ __half g_woh[DD*DD];
__device__ __half g_q  [BB*HH*SS*HD];   // [bh][s][d] (pre-scaled by 0.125)
__device__ __half g_k  [BB*HH*SS*HD];   // [bh][s][d]
__device__ __half g_vt [BB*HH*HD*SS];   // [bh][d][s]
__device__ __half g_ctx[BB*SS*DD];      // [b][s][D] (half)

__device__ __forceinline__ void mma16(float* c, uint32_t a0, uint32_t a1,
                                      uint32_t a2, uint32_t a3,
                                      uint32_t b0, uint32_t b1) {
    asm volatile(
        "mma.sync.aligned.m16n8k16.row.col.f32.f16.f16.f32 "
        "{%0,%1,%2,%3}, {%4,%5,%6,%7}, {%8,%9}, {%0,%1,%2,%3};"
        : "+f"(c[0]), "+f"(c[1]), "+f"(c[2]), "+f"(c[3])
        : "r"(a0), "r"(a1), "r"(a2), "r"(a3), "r"(b0), "r"(b1));
}
__device__ __forceinline__ void ldmx4(uint32_t* r, uint32_t addr) {
    asm volatile("ldmatrix.sync.aligned.m8n8.x4.shared.b16 {%0,%1,%2,%3}, [%4];"
        : "=r"(r[0]), "=r"(r[1]), "=r"(r[2]), "=r"(r[3]) : "r"(addr));
}
__device__ __forceinline__ void cpa16(uint32_t s, const void* g) {
    asm volatile("cp.async.cg.shared.global [%0], [%1], 16;" :: "r"(s), "l"(g));
}
__device__ __forceinline__ void cp_commit() {
    asm volatile("cp.async.commit_group;");
}
__device__ __forceinline__ void cp_wait0() {
    asm volatile("cp.async.wait_group 0;");
}

// ---------------------------------------------------------------------------
// f32 -> f16 conversion (n multiple of 4)
// ---------------------------------------------------------------------------
__global__ void f2h(const float* __restrict__ src, __half* __restrict__ dst, int n) {
    int i = (blockIdx.x * blockDim.x + threadIdx.x) * 4;
    if (i < n) {
        float4 v = *(const float4*)(src + i);
        *(__half2*)(dst + i)     = __floats2half2_rn(v.x, v.y);
        *(__half2*)(dst + i + 2) = __floats2half2_rn(v.z, v.w);
    }
}

// ---------------------------------------------------------------------------
// FP16 GEMM, half inputs, cp.async double buffer. C = A[M,K] @ W[N,K]^T.
// Block 128x128, BK=32, 256 thr = 8 warps (2m x 4n), warp tile 64x32.
// Smem row stride 40 halves (80 B) -> conflict-free ldmatrix + aligned cp.async.
// mode: 0 out-proj (A=g_ctx -> f32 out + bias); 1 Q(x0.125); 2 K; 3 V(transposed)
// ---------------------------------------------------------------------------
#define GS 40    // smem row stride (halves)

__global__ __launch_bounds__(256) void gemm_h(
    const __half* __restrict__ A, const __half* __restrict__ W,
    const float* __restrict__ bias, float* __restrict__ out, int mode)
{
    __shared__ __half As[2][128*GS];
    __shared__ __half Bs[2][128*GS];

    const int t = threadIdx.x;
    const int lane = t & 31;
    const int q = lane & 3, g = lane >> 2;
    const int warp = t >> 5;
    const int wm = warp & 1, wn = warp >> 1;
    const int m0 = blockIdx.y * 128, n0 = blockIdx.x * 128;

    // loader: row = t>>1, two 16B chunks (16 halves) per row half
    const int lr = t >> 1;
    const int lc = (t & 1) * 16;          // halves offset within 32-half slab

    const __half* Ag = A + (size_t)(m0 + lr) * DD + lc;
    const __half* Wg = W + (size_t)(n0 + lr) * DD + lc;

    const uint32_t asb[2] = { (uint32_t)__cvta_generic_to_shared(As[0]),
                              (uint32_t)__cvta_generic_to_shared(As[1]) };
    const uint32_t bsb[2] = { (uint32_t)__cvta_generic_to_shared(Bs[0]),
                              (uint32_t)__cvta_generic_to_shared(Bs[1]) };
    const uint32_t sa = lr * (GS*2) + lc * 2;   // smem byte offset for loader

    // ldmatrix per-lane offsets (bytes), stride 80 B
    const int a4off = (((lane & 7) + ((lane >> 3) & 1) * 8) * GS + (lane >> 4) * 8) * 2;
    const int b4off = (((lane & 7) + (lane >> 4) * 8) * GS + ((lane >> 3) & 1) * 8) * 2;

    float c[4][4][4] = {};

    // prologue: slab 0 -> buf 0
    cpa16(asb[0] + sa,      Ag);
    cpa16(asb[0] + sa + 16, Ag + 8);
    cpa16(bsb[0] + sa,      Wg);
    cpa16(bsb[0] + sa + 16, Wg + 8);
    cp_commit();

    const int NIT = DD / 32;   // 24
    for (int it = 0; it < NIT; it++) {
        const int cur = it & 1;
        cp_wait0();
        __syncthreads();
        if (it + 1 < NIT) {
            const int nxt = cur ^ 1;
            const int k0 = (it + 1) * 32;
            cpa16(asb[nxt] + sa,      Ag + k0);
            cpa16(asb[nxt] + sa + 16, Ag + k0 + 8);
            cpa16(bsb[nxt] + sa,      Wg + k0);
            cpa16(bsb[nxt] + sa + 16, Wg + k0 + 8);
            cp_commit();
        }

        #pragma unroll
        for (int ks = 0; ks < 2; ks++) {
            uint32_t a[4][4]; uint32_t b[2][4];
            #pragma unroll
            for (int mt = 0; mt < 4; mt++)
                ldmx4(a[mt], asb[cur] + (wm * 64 + mt * 16) * (GS*2) + a4off + ks * 32);
            #pragma unroll
            for (int np = 0; np < 2; np++)
                ldmx4(b[np], bsb[cur] + (wn * 32 + np * 16) * (GS*2) + b4off + ks * 32);
            #pragma unroll
            for (int mt = 0; mt < 4; mt++) {
                #pragma unroll
                for (int np = 0; np < 2; np++) {
                    mma16(c[mt][2*np],   a[mt][0], a[mt][1], a[mt][2], a[mt][3],
                          b[np][0], b[np][1]);
                    mma16(c[mt][2*np+1], a[mt][0], a[mt][1], a[mt][2], a[mt][3],
                          b[np][2], b[np][3]);
                }
            }
        }
    }

    // Epilogue
    #pragma unroll
    for (int mt = 0; mt < 4; mt++) {
        const int r0 = m0 + wm * 64 + mt * 16 + g;   // r1 = r0 + 8, same batch
        #pragma unroll
        for (int nt = 0; nt < 4; nt++) {
            const int cc = n0 + wn * 32 + nt * 8 + 2 * q;
            float* cf = c[mt][nt];
            if (mode == 0) {
                float2 bv = *(const float2*)(bias + cc);
                *(float2*)(out + (size_t)r0 * DD + cc) =
                    make_float2(cf[0] + bv.x, cf[1] + bv.y);
                *(float2*)(out + (size_t)(r0 + 8) * DD + cc) =
                    make_float2(cf[2] + bv.x, cf[3] + bv.y);
            } else {
                const int h = cc >> 6, d = cc & 63;
                const int bi = r0 >> 11, s0 = r0 & (SS - 1), s1 = s0 + 8;
                if (mode == 3) {
                    __half* dst = g_vt + ((size_t)((bi * HH + h) * HD + d)) * SS;
                    dst[s0]      = __float2half(cf[0]);
                    dst[SS + s0] = __float2half(cf[1]);
                    dst[s1]      = __float2half(cf[2]);
                    dst[SS + s1] = __float2half(cf[3]);
                } else {
                    const float sc = (mode == 1) ? 0.125f : 1.0f;
                    __half* dst = (mode == 1) ? g_q : g_k;
                    *(__half2*)(dst + ((size_t)(bi * HH + h) * SS + s0) * HD + d) =
                        __floats2half2_rn(cf[0] * sc, cf[1] * sc);
                    *(__half2*)(dst + ((size_t)(bi * HH + h) * SS + s1) * HD + d) =
                        __floats2half2_rn(cf[2] * sc, cf[3] * sc);
                }
            }
        }
    }
}

// ---------------------------------------------------------------------------
// FP16 flash attention, causal, cp.async double-buffered K/V.
// Block = 128 q-rows x 64 kv tile, 8 warps; warp w owns q-rows 16w..16w+15.
// ---------------------------------------------------------------------------
#define AS 72                       // attn smem row stride (halves), 144 B
#define ATTN_SMEM_BYTES ((4 * 64 * AS + 128 * AS) * 2)   // 55296 B

__global__ __launch_bounds__(256) void attn_h()
{
    extern __shared__ __half smh[];
    __half* Ks0 = smh;                  // [64][AS] buf0
    __half* Ks1 = smh +  64 * AS;
    __half* Vt0 = smh + 128 * AS;
    __half* Vt1 = smh + 192 * AS;
    __half* Ps  = smh + 256 * AS;       // [128][AS]: Q staging, then per-warp P

    const int t = threadIdx.x;
    const int lane = t & 31;
    const int q = lane & 3, g = lane >> 2;
    const int w = t >> 5;
    const int qtb = gridDim.x - 1 - blockIdx.x;   // heavy blocks first
    const int bh = blockIdx.y;

    const int krow = t & 63, kuq = t >> 6;        // loader: row + chunk quarter
    const int qrow = t & 127, quh = t >> 7;

    const uint32_t ksb[2] = { (uint32_t)__cvta_generic_to_shared(Ks0),
                              (uint32_t)__cvta_generic_to_shared(Ks1) };
    const uint32_t vtb[2] = { (uint32_t)__cvta_generic_to_shared(Vt0),
                              (uint32_t)__cvta_generic_to_shared(Vt1) };
    const uint32_t ps_b = (uint32_t)__cvta_generic_to_shared(Ps);

    const int a4off = (((lane & 7) + ((lane >> 3) & 1) * 8) * AS + (lane >> 4) * 8) * 2;
    const int b4off = (((lane & 7) + (lane >> 4) * 8) * AS + ((lane >> 3) & 1) * 8) * 2;

    const __half* Kg = g_k  + (size_t)bh * SS * HD;
    const __half* Vg = g_vt + (size_t)bh * HD * SS;
    const uint32_t kso = krow * (AS*2) + kuq * 16;   // loader smem byte offset
    const int ntiles = 2 * qtb + 2;

    // prologue: tile 0 -> buf 0 (async), then stage Q synchronously
    {
        const __half* kp = Kg + (size_t)krow * HD + kuq * 8;
        const __half* vp = Vg + (size_t)krow * SS + kuq * 8;
        cpa16(ksb[0] + kso,      kp);
        cpa16(ksb[0] + kso + 64, kp + 32);
        cpa16(vtb[0] + kso,      vp);
        cpa16(vtb[0] + kso + 64, vp + 32);
        cp_commit();
    }
    {
        const uint4* Qg = (const uint4*)(g_q + ((size_t)bh * SS + qtb * 128 + qrow) * HD);
        uint4* Pd = (uint4*)&Ps[qrow * AS];
        #pragma unroll
        for (int i = 0; i < 4; i++) {
            int c8 = quh + 2 * i;
            Pd[c8] = Qg[c8];
        }
    }
    __syncthreads();

    // Q fragments -> registers (persistent)
    uint32_t qa[4][4];
    #pragma unroll
    for (int ks = 0; ks < 4; ks++)
        ldmx4(qa[ks], ps_b + w * 16 * (AS*2) + a4off + ks * 32);

    float o[8][4] = {};
    float m0 = -INFINITY, m1 = -INFINITY, l0 = 0.f, l1 = 0.f;

    const int row0g = 128 * qtb + 16 * w + g;
    const int row1g = row0g + 8;

    __half2* Pr0 = (__half2*)&Ps[(16 * w + g) * AS];
    __half2* Pr1 = (__half2*)&Ps[(16 * w + g + 8) * AS];

    for (int kt = 0; kt < ntiles; kt++) {
        const int cur = kt & 1;
        cp_wait0();
        __syncthreads();        // tile kt visible to all
        if (kt + 1 < ntiles) {  // prefetch next tile into other buffer
            const int nxt = cur ^ 1;
            const __half* kp = Kg + (size_t)(64 * (kt + 1) + krow) * HD + kuq * 8;
            const __half* vp = Vg + (size_t)krow * SS + 64 * (kt + 1) + kuq * 8;
            cpa16(ksb[nxt] + kso,      kp);
            cpa16(ksb[nxt] + kso + 64, kp + 32);
            cpa16(vtb[nxt] + kso,      vp);
            cpa16(vtb[nxt] + kso + 64, vp + 32);
            cp_commit();
        }

        // tile entirely above this warp's rows -> nothing to do
        if (64 * kt > 128 * qtb + 16 * w + 15) continue;

        // ---- S = Q K^T : 16 x 64 per warp ----
        float s4[8][4] = {};
        #pragma unroll
        for (int ks = 0; ks < 4; ks++) {
            #pragma unroll
            for (int np = 0; np < 4; np++) {
                uint32_t b[4];
                ldmx4(b, ksb[cur] + np * 16 * (AS*2) + b4off + ks * 32);
                mma16(s4[2*np],   qa[ks][0], qa[ks][1], qa[ks][2], qa[ks][3], b[0], b[1]);
                mma16(s4[2*np+1], qa[ks][0], qa[ks][1], qa[ks][2], qa[ks][3], b[2], b[3]);
            }
        }

        // causal mask on straddling tiles
        if (64 * kt + 63 > 128 * qtb + 16 * w) {
            #pragma unroll
            for (int nt = 0; nt < 8; nt++) {
                int colg = 64 * kt + 8 * nt + 2 * q;
                if (colg     > row0g) s4[nt][0] = -INFINITY;
                if (colg + 1 > row0g) s4[nt][1] = -INFINITY;
                if (colg     > row1g) s4[nt][2] = -INFINITY;
                if (colg + 1 > row1g) s4[nt][3] = -INFINITY;
            }
        }

        // ---- warp-local online softmax ----
        float pm0 = -INFINITY, pm1 = -INFINITY;
        #pragma unroll
        for (int nt = 0; nt < 8; nt++) {
            pm0 = fmaxf(pm0, fmaxf(s4[nt][0], s4[nt][1]));
            pm1 = fmaxf(pm1, fmaxf(s4[nt][2], s4[nt][3]));
        }
        pm0 = fmaxf(pm0, __shfl_xor_sync(0xffffffffu, pm0, 1));
        pm0 = fmaxf(pm0, __shfl_xor_sync(0xffffffffu, pm0, 2));
        pm1 = fmaxf(pm1, __shfl_xor_sync(0xffffffffu, pm1, 1));
        pm1 = fmaxf(pm1, __shfl_xor_sync(0xffffffffu, pm1, 2));

        const float mn0 = fmaxf(m0, pm0), mn1 = fmaxf(m1, pm1);
        const float al0 = __expf(m0 - mn0), al1 = __expf(m1 - mn1);
        m0 = mn0; m1 = mn1;

        float sum0 = 0.f, sum1 = 0.f;
        #pragma unroll
        for (int nt = 0; nt < 8; nt++) {
            float p0 = __expf(s4[nt][0] - mn0), p1 = __expf(s4[nt][1] - mn0);
            float p2 = __expf(s4[nt][2] - mn1), p3 = __expf(s4[nt][3] - mn1);
            sum0 += p0 + p1; sum1 += p2 + p3;
            Pr0[4 * nt + q] = __floats2half2_rn(p0, p1);
            Pr1[4 * nt + q] = __floats2half2_rn(p2, p3);
        }
        sum0 += __shfl_xor_sync(0xffffffffu, sum0, 1);
        sum0 += __shfl_xor_sync(0xffffffffu, sum0, 2);
        sum1 += __shfl_xor_sync(0xffffffffu, sum1, 1);
        sum1 += __shfl_xor_sync(0xffffffffu, sum1, 2);
        l0 = l0 * al0 + sum0;
        l1 = l1 * al1 + sum1;

        #pragma unroll
        for (int nd = 0; nd < 8; nd++) {
            o[nd][0] *= al0; o[nd][1] *= al0; o[nd][2] *= al1; o[nd][3] *= al1;
        }
        __syncwarp();   // P stores visible before ldmatrix reads

        // ---- O += P V ----
        uint32_t pf[4][4];
        #pragma unroll
        for (int ks = 0; ks < 4; ks++)
            ldmx4(pf[ks], ps_b + w * 16 * (AS*2) + a4off + ks * 32);
        #pragma unroll
        for (int ks = 0; ks < 4; ks++) {
            #pragma unroll
            for (int np = 0; np < 4; np++) {
                uint32_t b[4];
                ldmx4(b, vtb[cur] + np * 16 * (AS*2) + b4off + ks * 32);
                mma16(o[2*np],   pf[ks][0], pf[ks][1], pf[ks][2], pf[ks][3], b[0], b[1]);
                mma16(o[2*np+1], pf[ks][0], pf[ks][1], pf[ks][2], pf[ks][3], b[2], b[3]);
            }
        }
        __syncwarp();   // reads done before next tile's P stores
    }

    // ---- epilogue: normalize, write ctx [b][s][D] (half) ----
    const float inv0 = 1.0f / l0, inv1 = 1.0f / l1;
    const int b = bh / HH, h = bh % HH;
    const int s0 = 128 * qtb + 16 * w + g, s1 = s0 + 8;
    __half* C0 = g_ctx + ((size_t)b * SS + s0) * DD + h * HD;
    __half* C1 = g_ctx + ((size_t)b * SS + s1) * DD + h * HD;
    #pragma unroll
    for (int nd = 0; nd < 8; nd++) {
        int cc = 8 * nd + 2 * q;
        *(__half2*)(C0 + cc) = __floats2half2_rn(o[nd][0] * inv0, o[nd][1] * inv0);
        *(__half2*)(C1 + cc) = __floats2half2_rn(o[nd][2] * inv1, o[nd][3] * inv1);
    }
}

// ---------------------------------------------------------------------------
extern "C" void kernel_launch(void* const* d_in, const int* in_sizes, int n_in,
                              void* d_out, int out_size)
{
    const float* x  = (const float*)d_in[0];
    const float* wq = (const float*)d_in[1];
    const float* wk = (const float*)d_in[2];
    const float* wv = (const float*)d_in[3];
    const float* wo = (const float*)d_in[4];
    const float* bo = (const float*)d_in[5];
    float* out = (float*)d_out;

    cudaFuncSetAttribute(attn_h,
                         cudaFuncAttributeMaxDynamicSharedMemorySize,
                         ATTN_SMEM_BYTES);

    __half *xh, *wqh, *wkh, *wvh, *woh;
    cudaGetSymbolAddress((void**)&xh,  g_xh);
    cudaGetSymbolAddress((void**)&wqh, g_wqh);
    cudaGetSymbolAddress((void**)&wkh, g_wkh);
    cudaGetSymbolAddress((void**)&wvh, g_wvh);
    cudaGetSymbolAddress((void**)&woh, g_woh);

    const int NX = BB * SS * DD;   // 6291456
    const int NW = DD * DD;        // 589824
    f2h<<<NX / 1024, 256>>>(x,  xh,  NX);
    f2h<<<NW / 1024, 256>>>(wq, wqh, NW);
    f2h<<<NW / 1024, 256>>>(wk, wkh, NW);
    f2h<<<NW / 1024, 256>>>(wv, wvh, NW);
    f2h<<<NW / 1024, 256>>>(wo, woh, NW);

    dim3 blk(256);
    dim3 gproj(DD / 128, (BB * SS) / 128);   // (6, 64)

    gemm_h<<<gproj, blk>>>(xh, wqh, nullptr, nullptr, 1);
    gemm_h<<<gproj, blk>>>(xh, wkh, nullptr, nullptr, 2);
    gemm_h<<<gproj, blk>>>(xh, wvh, nullptr, nullptr, 3);

    attn_h<<<dim3(SS / 128, BB * HH), blk, ATTN_SMEM_BYTES>>>();

    __half* ctxh;
    cudaGetSymbolAddress((void**)&ctxh, g_ctx);
    gemm_h<<<gproj, blk>>>(ctxh, woh, bo, out, 0);
}

// round 11
// speedup vs baseline: 6.9935x; 1.1706x over previous
#include <cuda_runtime.h>
#include <cuda_fp16.h>
#include <math.h>
#include <stdint.h>

#define BB 4
#define SS 2048
#define DD 768
#define HH 12
#define HD 64

#define QSCALE 0.18033688f   // 0.125 * log2(e)

// half scratch
__device__ __half g_xh [BB*SS*DD];
__device__ __half g_wqh[DD*DD];
__device__ __half g_wkh[DD*DD];
__device__ __half g_wvh[DD*DD];
__device__ __half g_woh[DD*DD];
__device__ __half g_q  [BB*HH*SS*HD];   // [bh][s][d] (pre-scaled by QSCALE)
__device__ __half g_k  [BB*HH*SS*HD];   // [bh][s][d]
__device__ __half g_vt [BB*HH*HD*SS];   // [bh][d][s]
__device__ __half g_ctx[BB*SS*DD];      // [b][s][D]

__device__ __forceinline__ void mma16(float* c, uint32_t a0, uint32_t a1,
                                      uint32_t a2, uint32_t a3,
                                      uint32_t b0, uint32_t b1) {
    asm volatile(
        "mma.sync.aligned.m16n8k16.row.col.f32.f16.f16.f32 "
        "{%0,%1,%2,%3}, {%4,%5,%6,%7}, {%8,%9}, {%0,%1,%2,%3};"
        : "+f"(c[0]), "+f"(c[1]), "+f"(c[2]), "+f"(c[3])
        : "r"(a0), "r"(a1), "r"(a2), "r"(a3), "r"(b0), "r"(b1));
}
__device__ __forceinline__ void ldmx4(uint32_t* r, uint32_t addr) {
    asm volatile("ldmatrix.sync.aligned.m8n8.x4.shared.b16 {%0,%1,%2,%3}, [%4];"
        : "=r"(r[0]), "=r"(r[1]), "=r"(r[2]), "=r"(r[3]) : "r"(addr));
}
__device__ __forceinline__ void cpa16(uint32_t s, const void* g) {
    asm volatile("cp.async.cg.shared.global [%0], [%1], 16;" :: "r"(s), "l"(g));
}
__device__ __forceinline__ void cp_commit() { asm volatile("cp.async.commit_group;"); }
__device__ __forceinline__ void cp_wait0()  { asm volatile("cp.async.wait_group 0;"); }

__device__ __forceinline__ uint32_t packh2(float a, float b) {
    __half2 h = __floats2half2_rn(a, b);
    return *(uint32_t*)&h;
}

// ---------------------------------------------------------------------------
__global__ void f2h(const float* __restrict__ src, __half* __restrict__ dst, int n) {
    int i = (blockIdx.x * blockDim.x + threadIdx.x) * 4;
    if (i < n) {
        float4 v = *(const float4*)(src + i);
        *(__half2*)(dst + i)     = __floats2half2_rn(v.x, v.y);
        *(__half2*)(dst + i + 2) = __floats2half2_rn(v.z, v.w);
    }
}

// ---------------------------------------------------------------------------
// Shared GEMM mainloop: 128x128 block, BK=32, cp.async double buffer.
// 8 warps (2m x 4n), warp tile 64x32, fp16 in / f32 accum.
// ---------------------------------------------------------------------------
#define GS 40    // smem row stride (halves)

struct GemmCtx {
    float c[4][4][4];
};

__device__ __forceinline__ void gemm_mainloop(
    const __half* Aposn, const __half* Wposn,
    __half (*As)[128*GS], __half (*Bs)[128*GS],
    int t, int lane, int wm, int wn, GemmCtx& G)
{
    const int lr = t >> 1;
    const int lc = (t & 1) * 16;
    const __half* Ag = Aposn + (size_t)lr * DD + lc;
    const __half* Wg = Wposn + (size_t)lr * DD + lc;

    const uint32_t asb[2] = { (uint32_t)__cvta_generic_to_shared(As[0]),
                              (uint32_t)__cvta_generic_to_shared(As[1]) };
    const uint32_t bsb[2] = { (uint32_t)__cvta_generic_to_shared(Bs[0]),
                              (uint32_t)__cvta_generic_to_shared(Bs[1]) };
    const uint32_t sa = lr * (GS*2) + lc * 2;

    const int a4off = (((lane & 7) + ((lane >> 3) & 1) * 8) * GS + (lane >> 4) * 8) * 2;
    const int b4off = (((lane & 7) + (lane >> 4) * 8) * GS + ((lane >> 3) & 1) * 8) * 2;

    cpa16(asb[0] + sa,      Ag);
    cpa16(asb[0] + sa + 16, Ag + 8);
    cpa16(bsb[0] + sa,      Wg);
    cpa16(bsb[0] + sa + 16, Wg + 8);
    cp_commit();

    const int NIT = DD / 32;   // 24
    for (int it = 0; it < NIT; it++) {
        const int cur = it & 1;
        cp_wait0();
        __syncthreads();
        if (it + 1 < NIT) {
            const int nxt = cur ^ 1;
            const int k0 = (it + 1) * 32;
            cpa16(asb[nxt] + sa,      Ag + k0);
            cpa16(asb[nxt] + sa + 16, Ag + k0 + 8);
            cpa16(bsb[nxt] + sa,      Wg + k0);
            cpa16(bsb[nxt] + sa + 16, Wg + k0 + 8);
            cp_commit();
        }
        #pragma unroll
        for (int ks = 0; ks < 2; ks++) {
            uint32_t a[4][4]; uint32_t b[2][4];
            #pragma unroll
            for (int mt = 0; mt < 4; mt++)
                ldmx4(a[mt], asb[cur] + (wm * 64 + mt * 16) * (GS*2) + a4off + ks * 32);
            #pragma unroll
            for (int np = 0; np < 2; np++)
                ldmx4(b[np], bsb[cur] + (wn * 32 + np * 16) * (GS*2) + b4off + ks * 32);
            #pragma unroll
            for (int mt = 0; mt < 4; mt++)
                #pragma unroll
                for (int np = 0; np < 2; np++) {
                    mma16(G.c[mt][2*np],   a[mt][0], a[mt][1], a[mt][2], a[mt][3],
                          b[np][0], b[np][1]);
                    mma16(G.c[mt][2*np+1], a[mt][0], a[mt][1], a[mt][2], a[mt][3],
                          b[np][2], b[np][3]);
                }
        }
    }
}

// ---------------------------------------------------------------------------
// Fused QKV projection: grid (18, 64). sel = bx/6 chooses Q/K/V.
// ---------------------------------------------------------------------------
__global__ __launch_bounds__(256) void gemm_qkv()
{
    __shared__ __half As[2][128*GS];
    __shared__ __half Bs[2][128*GS];

    const int t = threadIdx.x;
    const int lane = t & 31;
    const int q = lane & 3, g = lane >> 2;
    const int warp = t >> 5;
    const int wm = warp & 1, wn = warp >> 1;
    const int sel = blockIdx.x / 6;
    const int n0 = (blockIdx.x % 6) * 128;
    const int m0 = blockIdx.y * 128;

    const __half* W = (sel == 0) ? g_wqh : (sel == 1) ? g_wkh : g_wvh;

    GemmCtx G = {};
    gemm_mainloop(g_xh + (size_t)m0 * DD, W + (size_t)n0 * DD, As, Bs,
                  t, lane, wm, wn, G);

    #pragma unroll
    for (int mt = 0; mt < 4; mt++) {
        const int r0 = m0 + wm * 64 + mt * 16 + g;
        #pragma unroll
        for (int nt = 0; nt < 4; nt++) {
            const int cc = n0 + wn * 32 + nt * 8 + 2 * q;
            float* cf = G.c[mt][nt];
            const int h = cc >> 6, d = cc & 63;
            const int bi = r0 >> 11, s0 = r0 & (SS - 1), s1 = s0 + 8;
            if (sel == 2) {
                __half* dst = g_vt + ((size_t)((bi * HH + h) * HD + d)) * SS;
                dst[s0]      = __float2half(cf[0]);
                dst[SS + s0] = __float2half(cf[1]);
                dst[s1]      = __float2half(cf[2]);
                dst[SS + s1] = __float2half(cf[3]);
            } else {
                const float sc = (sel == 0) ? QSCALE : 1.0f;
                __half* dst = (sel == 0) ? g_q : g_k;
                *(__half2*)(dst + ((size_t)(bi * HH + h) * SS + s0) * HD + d) =
                    __floats2half2_rn(cf[0] * sc, cf[1] * sc);
                *(__half2*)(dst + ((size_t)(bi * HH + h) * SS + s1) * HD + d) =
                    __floats2half2_rn(cf[2] * sc, cf[3] * sc);
            }
        }
    }
}

// ---------------------------------------------------------------------------
// Out-projection: C = ctx @ wo^T + bias -> f32 out
// ---------------------------------------------------------------------------
__global__ __launch_bounds__(256) void gemm_out(
    const float* __restrict__ bias, float* __restrict__ out)
{
    __shared__ __half As[2][128*GS];
    __shared__ __half Bs[2][128*GS];

    const int t = threadIdx.x;
    const int lane = t & 31;
    const int q = lane & 3, g = lane >> 2;
    const int warp = t >> 5;
    const int wm = warp & 1, wn = warp >> 1;
    const int m0 = blockIdx.y * 128, n0 = blockIdx.x * 128;

    GemmCtx G = {};
    gemm_mainloop(g_ctx + (size_t)m0 * DD, g_woh + (size_t)n0 * DD, As, Bs,
                  t, lane, wm, wn, G);

    #pragma unroll
    for (int mt = 0; mt < 4; mt++) {
        const int r0 = m0 + wm * 64 + mt * 16 + g;
        #pragma unroll
        for (int nt = 0; nt < 4; nt++) {
            const int cc = n0 + wn * 32 + nt * 8 + 2 * q;
            float* cf = G.c[mt][nt];
            float2 bv = *(const float2*)(bias + cc);
            *(float2*)(out + (size_t)r0 * DD + cc) =
                make_float2(cf[0] + bv.x, cf[1] + bv.y);
            *(float2*)(out + (size_t)(r0 + 8) * DD + cc) =
                make_float2(cf[2] + bv.x, cf[3] + bv.y);
        }
    }
}

// ---------------------------------------------------------------------------
// FP16 flash attention, causal, cp.async double-buffered K/V.
// Block = 128 q-rows x 64 kv; warp w owns q-rows 16w..16w+15.
// P stays in registers: S C-fragment re-packed directly as PV A-fragment.
// ---------------------------------------------------------------------------
#define AS 72
#define ATTN_SMEM_BYTES ((4 * 64 * AS + 128 * AS) * 2)   // 55296 B

__global__ __launch_bounds__(256) void attn_h()
{
    extern __shared__ __half smh[];
    __half* Ks0 = smh;
    __half* Ks1 = smh +  64 * AS;
    __half* Vt0 = smh + 128 * AS;
    __half* Vt1 = smh + 192 * AS;
    __half* Ps  = smh + 256 * AS;       // Q staging only

    const int t = threadIdx.x;
    const int lane = t & 31;
    const int q = lane & 3, g = lane >> 2;
    const int w = t >> 5;
    const int qtb = gridDim.x - 1 - blockIdx.x;
    const int bh = blockIdx.y;

    const int krow = t & 63, kuq = t >> 6;
    const int qrow = t & 127, quh = t >> 7;

    const uint32_t ksb[2] = { (uint32_t)__cvta_generic_to_shared(Ks0),
                              (uint32_t)__cvta_generic_to_shared(Ks1) };
    const uint32_t vtb[2] = { (uint32_t)__cvta_generic_to_shared(Vt0),
                              (uint32_t)__cvta_generic_to_shared(Vt1) };
    const uint32_t ps_b = (uint32_t)__cvta_generic_to_shared(Ps);

    const int a4off = (((lane & 7) + ((lane >> 3) & 1) * 8) * AS + (lane >> 4) * 8) * 2;
    const int b4off = (((lane & 7) + (lane >> 4) * 8) * AS + ((lane >> 3) & 1) * 8) * 2;

    const __half* Kg = g_k  + (size_t)bh * SS * HD;
    const __half* Vg = g_vt + (size_t)bh * HD * SS;
    const uint32_t kso = krow * (AS*2) + kuq * 16;
    const int ntiles = 2 * qtb + 2;

    // prologue: tile 0 async; stage Q synchronously
    {
        const __half* kp = Kg + (size_t)krow * HD + kuq * 8;
        const __half* vp = Vg + (size_t)krow * SS + kuq * 8;
        cpa16(ksb[0] + kso,      kp);
        cpa16(ksb[0] + kso + 64, kp + 32);
        cpa16(vtb[0] + kso,      vp);
        cpa16(vtb[0] + kso + 64, vp + 32);
        cp_commit();
    }
    {
        const uint4* Qg = (const uint4*)(g_q + ((size_t)bh * SS + qtb * 128 + qrow) * HD);
        uint4* Pd = (uint4*)&Ps[qrow * AS];
        #pragma unroll
        for (int i = 0; i < 4; i++) {
            int c8 = quh + 2 * i;
            Pd[c8] = Qg[c8];
        }
    }
    __syncthreads();

    uint32_t qa[4][4];
    #pragma unroll
    for (int ks = 0; ks < 4; ks++)
        ldmx4(qa[ks], ps_b + w * 16 * (AS*2) + a4off + ks * 32);

    float o[8][4] = {};
    float m0 = -INFINITY, m1 = -INFINITY, l0 = 0.f, l1 = 0.f;

    const int row0g = 128 * qtb + 16 * w + g;
    const int row1g = row0g + 8;

    for (int kt = 0; kt < ntiles; kt++) {
        const int cur = kt & 1;
        cp_wait0();
        __syncthreads();
        if (kt + 1 < ntiles) {
            const int nxt = cur ^ 1;
            const __half* kp = Kg + (size_t)(64 * (kt + 1) + krow) * HD + kuq * 8;
            const __half* vp = Vg + (size_t)krow * SS + 64 * (kt + 1) + kuq * 8;
            cpa16(ksb[nxt] + kso,      kp);
            cpa16(ksb[nxt] + kso + 64, kp + 32);
            cpa16(vtb[nxt] + kso,      vp);
            cpa16(vtb[nxt] + kso + 64, vp + 32);
            cp_commit();
        }

        if (64 * kt > 128 * qtb + 16 * w + 15) continue;

        // ---- S = Q K^T ----
        float s4[8][4] = {};
        #pragma unroll
        for (int ks = 0; ks < 4; ks++) {
            #pragma unroll
            for (int np = 0; np < 4; np++) {
                uint32_t b[4];
                ldmx4(b, ksb[cur] + np * 16 * (AS*2) + b4off + ks * 32);
                mma16(s4[2*np],   qa[ks][0], qa[ks][1], qa[ks][2], qa[ks][3], b[0], b[1]);
                mma16(s4[2*np+1], qa[ks][0], qa[ks][1], qa[ks][2], qa[ks][3], b[2], b[3]);
            }
        }

        if (64 * kt + 63 > 128 * qtb + 16 * w) {
            #pragma unroll
            for (int nt = 0; nt < 8; nt++) {
                int colg = 64 * kt + 8 * nt + 2 * q;
                if (colg     > row0g) s4[nt][0] = -INFINITY;
                if (colg + 1 > row0g) s4[nt][1] = -INFINITY;
                if (colg     > row1g) s4[nt][2] = -INFINITY;
                if (colg + 1 > row1g) s4[nt][3] = -INFINITY;
            }
        }

        // ---- warp-local online softmax (base-2 domain) ----
        float pm0 = -INFINITY, pm1 = -INFINITY;
        #pragma unroll
        for (int nt = 0; nt < 8; nt++) {
            pm0 = fmaxf(pm0, fmaxf(s4[nt][0], s4[nt][1]));
            pm1 = fmaxf(pm1, fmaxf(s4[nt][2], s4[nt][3]));
        }
        pm0 = fmaxf(pm0, __shfl_xor_sync(0xffffffffu, pm0, 1));
        pm0 = fmaxf(pm0, __shfl_xor_sync(0xffffffffu, pm0, 2));
        pm1 = fmaxf(pm1, __shfl_xor_sync(0xffffffffu, pm1, 1));
        pm1 = fmaxf(pm1, __shfl_xor_sync(0xffffffffu, pm1, 2));

        const float mn0 = fmaxf(m0, pm0), mn1 = fmaxf(m1, pm1);
        const float al0 = exp2f(m0 - mn0), al1 = exp2f(m1 - mn1);
        m0 = mn0; m1 = mn1;

        // P = exp2(S - m) packed straight into PV A-fragments (no smem!)
        uint32_t ph[8][2];
        float sum0 = 0.f, sum1 = 0.f;
        #pragma unroll
        for (int nt = 0; nt < 8; nt++) {
            float p0 = exp2f(s4[nt][0] - mn0), p1 = exp2f(s4[nt][1] - mn0);
            float p2 = exp2f(s4[nt][2] - mn1), p3 = exp2f(s4[nt][3] - mn1);
            sum0 += p0 + p1; sum1 += p2 + p3;
            ph[nt][0] = packh2(p0, p1);
            ph[nt][1] = packh2(p2, p3);
        }
        sum0 += __shfl_xor_sync(0xffffffffu, sum0, 1);
        sum0 += __shfl_xor_sync(0xffffffffu, sum0, 2);
        sum1 += __shfl_xor_sync(0xffffffffu, sum1, 1);
        sum1 += __shfl_xor_sync(0xffffffffu, sum1, 2);
        l0 = l0 * al0 + sum0;
        l1 = l1 * al1 + sum1;

        #pragma unroll
        for (int nd = 0; nd < 8; nd++) {
            o[nd][0] *= al0; o[nd][1] *= al0; o[nd][2] *= al1; o[nd][3] *= al1;
        }

        // ---- O += P V (A-fragments direct from registers) ----
        #pragma unroll
        for (int ks = 0; ks < 4; ks++) {
            #pragma unroll
            for (int np = 0; np < 4; np++) {
                uint32_t b[4];
                ldmx4(b, vtb[cur] + np * 16 * (AS*2) + b4off + ks * 32);
                mma16(o[2*np],   ph[2*ks][0], ph[2*ks][1], ph[2*ks+1][0], ph[2*ks+1][1],
                      b[0], b[1]);
                mma16(o[2*np+1], ph[2*ks][0], ph[2*ks][1], ph[2*ks+1][0], ph[2*ks+1][1],
                      b[2], b[3]);
            }
        }
    }

    // ---- epilogue ----
    const float inv0 = 1.0f / l0, inv1 = 1.0f / l1;
    const int b = bh / HH, h = bh % HH;
    const int s0 = 128 * qtb + 16 * w + g, s1 = s0 + 8;
    __half* C0 = g_ctx + ((size_t)b * SS + s0) * DD + h * HD;
    __half* C1 = g_ctx + ((size_t)b * SS + s1) * DD + h * HD;
    #pragma unroll
    for (int nd = 0; nd < 8; nd++) {
        int cc = 8 * nd + 2 * q;
        *(__half2*)(C0 + cc) = __floats2half2_rn(o[nd][0] * inv0, o[nd][1] * inv0);
        *(__half2*)(C1 + cc) = __floats2half2_rn(o[nd][2] * inv1, o[nd][3] * inv1);
    }
}

// ---------------------------------------------------------------------------
extern "C" void kernel_launch(void* const* d_in, const int* in_sizes, int n_in,
                              void* d_out, int out_size)
{
    const float* x  = (const float*)d_in[0];
    const float* wq = (const float*)d_in[1];
    const float* wk = (const float*)d_in[2];
    const float* wv = (const float*)d_in[3];
    const float* wo = (const float*)d_in[4];
    const float* bo = (const float*)d_in[5];
    float* out = (float*)d_out;

    cudaFuncSetAttribute(attn_h,
                         cudaFuncAttributeMaxDynamicSharedMemorySize,
                         ATTN_SMEM_BYTES);

    __half *xh, *wqh, *wkh, *wvh, *woh;
    cudaGetSymbolAddress((void**)&xh,  g_xh);
    cudaGetSymbolAddress((void**)&wqh, g_wqh);
    cudaGetSymbolAddress((void**)&wkh, g_wkh);
    cudaGetSymbolAddress((void**)&wvh, g_wvh);
    cudaGetSymbolAddress((void**)&woh, g_woh);

    const int NX = BB * SS * DD;
    const int NW = DD * DD;
    f2h<<<NX / 1024, 256>>>(x,  xh,  NX);
    f2h<<<NW / 1024, 256>>>(wq, wqh, NW);
    f2h<<<NW / 1024, 256>>>(wk, wkh, NW);
    f2h<<<NW / 1024, 256>>>(wv, wvh, NW);
    f2h<<<NW / 1024, 256>>>(wo, woh, NW);

    dim3 blk(256);

    gemm_qkv<<<dim3(18, (BB * SS) / 128), blk>>>();

    attn_h<<<dim3(SS / 128, BB * HH), blk, ATTN_SMEM_BYTES>>>();

    gemm_out<<<dim3(DD / 128, (BB * SS) / 128), blk>>>(bo, out);
}